// round 7
// baseline (speedup 1.0000x reference)
#include <cuda_runtime.h>
#include <cuda_bf16.h>
#include <cstdint>

#define N_NODES 100000
#define N_EDGES 300000
#define N_GRAPHS 2048
#define IN_DIM 38
#define HID 256
#define LAYERS 5
#define BN_EPS 1e-5f

// ---------------- device scratch ----------------
__device__ float g_h[N_NODES * HID];          // fp32 features (proj out)
__device__ float g_z[N_NODES * HID];          // GEMM2 output (pre-BN)
__device__ uint32_t g_zp[N_NODES * HID];      // packed (bf16hi,bf16lo) GEMM1 input
__device__ uint32_t g_tp[N_NODES * HID];      // packed GEMM1 out / GEMM2 in
__device__ __nv_bfloat16 g_whi[2 * LAYERS * HID * HID];  // W^T hi, [mat][n][k]
__device__ __nv_bfloat16 g_wlo[2 * LAYERS * HID * HID];  // W^T lo
__device__ float g_colsum2[2][HID];
__device__ float g_colsq2[2][HID];
__device__ float g_pool[N_GRAPHS * HID];
__device__ float g_r1[N_GRAPHS * HID];
__device__ int g_deg[N_NODES];
__device__ int g_fill[N_NODES];
__device__ int g_off[N_NODES + 1];
__device__ int g_csr[N_EDGES];

__device__ __forceinline__ uint32_t smem_u32(const void* p) {
    uint32_t a;
    asm("{ .reg .u64 t; cvta.to.shared.u64 t, %1; cvt.u32.u64 %0, t; }"
        : "=r"(a) : "l"(p));
    return a;
}

__device__ __forceinline__ uint32_t pack_split(float v) {
    __nv_bfloat16 h = __float2bfloat16(v);
    float res = v - __bfloat162float(h);
    __nv_bfloat16 l = __float2bfloat16(res);
    return (uint32_t)(*reinterpret_cast<uint16_t*>(&h)) |
           ((uint32_t)(*reinterpret_cast<uint16_t*>(&l)) << 16);
}

#define MMA_BF16(c, a0, a1, a2, a3, b0, b1)                                    \
    asm volatile(                                                              \
        "mma.sync.aligned.m16n8k16.row.col.f32.bf16.bf16.f32 "                 \
        "{%0,%1,%2,%3}, {%4,%5,%6,%7}, {%8,%9}, {%0,%1,%2,%3};"                \
        : "+f"((c)[0]), "+f"((c)[1]), "+f"((c)[2]), "+f"((c)[3])               \
        : "r"(a0), "r"(a1), "r"(a2), "r"(a3), "r"(b0), "r"(b1))

#define CP_ASYNC16(dst, src) \
    asm volatile("cp.async.ca.shared.global [%0], [%1], 16;" \
                 :: "r"(dst), "l"(src) : "memory")
#define CP_ASYNC16_Z(dst, src, n) \
    asm volatile("cp.async.ca.shared.global [%0], [%1], 16, %2;" \
                 :: "r"(dst), "l"(src), "r"(n) : "memory")
#define CP_COMMIT() asm volatile("cp.async.commit_group;" ::: "memory")

// stage: A packed 128 rows x 160B = 20480B; BH 256 x 80B = 20480; BL = 20480
#define STG 61440
#define A_ST(s)  ((s) * STG)
#define BH_ST(s) ((s) * STG + 20480)
#define BL_ST(s) ((s) * STG + 40960)
#define GEMM_SMEM (3 * STG)

// ====== GEMM: C[M,256] = unpack(Ap) @ (Whi+Wlo)[n][k]^T + bias (3-term split) ======
// Full N=256 per block. OUTMODE 0: fp32 out + fused stats; 1: relu + packed out.
template <int OUTMODE>
__global__ void __launch_bounds__(256, 1)
gemm_mma_kernel(const uint32_t* __restrict__ Ap,
                const __nv_bfloat16* __restrict__ Whi,
                const __nv_bfloat16* __restrict__ Wlo,
                const float* __restrict__ bias,
                void* __restrict__ Cout,
                float* __restrict__ colsum, float* __restrict__ colsq, int M) {
    extern __shared__ char sm[];
    const uint32_t smb = smem_u32(sm);
    const int tid = threadIdx.x;
    const int lane = tid & 31;
    const int wid = tid >> 5;
    const int wm = wid & 3;      // 4 row groups of 32
    const int wn = wid >> 2;     // 2 col groups of 128
    const int gq = lane >> 2;
    const int tq = lane & 3;
    const int row0 = blockIdx.x * 128;

    float acc[2][16][4];
#pragma unroll
    for (int i = 0; i < 2; i++)
#pragma unroll
        for (int n = 0; n < 16; n++)
#pragma unroll
            for (int q = 0; q < 4; q++) acc[i][n][q] = 0.f;

    auto load_chunk = [&](int c, int s) {
        const int k0 = c * 32;
        // A: 128 rows x 128B packed
#pragma unroll
        for (int i = 0; i < 4; i++) {
            int idx = tid + 256 * i;
            int r = idx >> 3, q = idx & 7;
            int gr = row0 + r;
            int nb = (gr < M) ? 16 : 0;
            int grc = (gr < M) ? gr : (M - 1);
            const char* src = (const char*)(Ap + (size_t)grc * HID + k0 + q * 4);
            CP_ASYNC16_Z(smb + A_ST(s) + r * 160 + q * 16, src, nb);
        }
        // B hi/lo: 256 n-rows x 64B each
#pragma unroll
        for (int i = 0; i < 8; i++) {
            int idx = tid + 256 * i;
            int half = idx >> 10, i2 = idx & 1023;
            int r = i2 >> 2, q = i2 & 3;
            const __nv_bfloat16* W = half ? Wlo : Whi;
            const char* src = (const char*)(W + (size_t)r * HID + k0 + q * 8);
            uint32_t dst = smb + (half ? BL_ST(s) : BH_ST(s)) + r * 80 + q * 16;
            CP_ASYNC16(dst, src);
        }
        CP_COMMIT();
    };

    auto compute = [&](int s) {
#pragma unroll
        for (int j = 0; j < 2; j++) {
            uint32_t ah[2][4], al[2][4];
#pragma unroll
            for (int i = 0; i < 2; i++) {
                int rb = wm * 32 + i * 16;
                const char* pA = sm + A_ST(s);
                uint2 q0 = *reinterpret_cast<const uint2*>(pA + (rb + gq) * 160 + j * 64 + tq * 8);
                uint2 q1 = *reinterpret_cast<const uint2*>(pA + (rb + 8 + gq) * 160 + j * 64 + tq * 8);
                uint2 q2 = *reinterpret_cast<const uint2*>(pA + (rb + gq) * 160 + j * 64 + tq * 8 + 32);
                uint2 q3 = *reinterpret_cast<const uint2*>(pA + (rb + 8 + gq) * 160 + j * 64 + tq * 8 + 32);
                ah[i][0] = __byte_perm(q0.x, q0.y, 0x5410);
                al[i][0] = __byte_perm(q0.x, q0.y, 0x7632);
                ah[i][1] = __byte_perm(q1.x, q1.y, 0x5410);
                al[i][1] = __byte_perm(q1.x, q1.y, 0x7632);
                ah[i][2] = __byte_perm(q2.x, q2.y, 0x5410);
                al[i][2] = __byte_perm(q2.x, q2.y, 0x7632);
                ah[i][3] = __byte_perm(q3.x, q3.y, 0x5410);
                al[i][3] = __byte_perm(q3.x, q3.y, 0x7632);
            }
#pragma unroll
            for (int n = 0; n < 16; n++) {
                int cb = wn * 128 + n * 8 + gq;
                uint32_t bh0 = *reinterpret_cast<const uint32_t*>(sm + BH_ST(s) + cb * 80 + j * 32 + tq * 4);
                uint32_t bh1 = *reinterpret_cast<const uint32_t*>(sm + BH_ST(s) + cb * 80 + j * 32 + tq * 4 + 16);
                uint32_t bl0 = *reinterpret_cast<const uint32_t*>(sm + BL_ST(s) + cb * 80 + j * 32 + tq * 4);
                uint32_t bl1 = *reinterpret_cast<const uint32_t*>(sm + BL_ST(s) + cb * 80 + j * 32 + tq * 4 + 16);
                MMA_BF16(acc[0][n], ah[0][0], ah[0][1], ah[0][2], ah[0][3], bh0, bh1);
                MMA_BF16(acc[1][n], ah[1][0], ah[1][1], ah[1][2], ah[1][3], bh0, bh1);
                MMA_BF16(acc[0][n], al[0][0], al[0][1], al[0][2], al[0][3], bh0, bh1);
                MMA_BF16(acc[1][n], al[1][0], al[1][1], al[1][2], al[1][3], bh0, bh1);
                MMA_BF16(acc[0][n], ah[0][0], ah[0][1], ah[0][2], ah[0][3], bl0, bl1);
                MMA_BF16(acc[1][n], ah[1][0], ah[1][1], ah[1][2], ah[1][3], bl0, bl1);
            }
        }
    };

    load_chunk(0, 0);
    load_chunk(1, 1);
    load_chunk(2, 2);

#pragma unroll 1
    for (int c = 0; c < 8; c++) {
        if (c <= 5)      asm volatile("cp.async.wait_group 2;" ::: "memory");
        else if (c == 6) asm volatile("cp.async.wait_group 1;" ::: "memory");
        else             asm volatile("cp.async.wait_group 0;" ::: "memory");
        __syncthreads();
        compute(c % 3);
        __syncthreads();
        if (c + 3 < 8) load_chunk(c + 3, c % 3);
    }

    // ---------------- epilogue ----------------
    if (OUTMODE == 1) {
        uint32_t* C = (uint32_t*)Cout;
#pragma unroll
        for (int i = 0; i < 2; i++) {
            int r0 = row0 + wm * 32 + i * 16 + gq;
#pragma unroll
            for (int n = 0; n < 16; n++) {
                int col = wn * 128 + n * 8 + tq * 2;
                float b0 = bias[col], b1 = bias[col + 1];
                float v0 = fmaxf(acc[i][n][0] + b0, 0.f);
                float v1 = fmaxf(acc[i][n][1] + b1, 0.f);
                float v2 = fmaxf(acc[i][n][2] + b0, 0.f);
                float v3 = fmaxf(acc[i][n][3] + b1, 0.f);
                if (r0 < M) {
                    uint2 p = make_uint2(pack_split(v0), pack_split(v1));
                    *reinterpret_cast<uint2*>(C + (size_t)r0 * HID + col) = p;
                }
                if (r0 + 8 < M) {
                    uint2 p = make_uint2(pack_split(v2), pack_split(v3));
                    *reinterpret_cast<uint2*>(C + (size_t)(r0 + 8) * HID + col) = p;
                }
            }
        }
    } else {
        float* C = (float*)Cout;
#pragma unroll
        for (int n = 0; n < 16; n++) {
            int col = wn * 128 + n * 8 + tq * 2;
            float b0 = bias[col], b1 = bias[col + 1];
            float s0 = 0.f, s1 = 0.f, q0 = 0.f, q1 = 0.f;
#pragma unroll
            for (int i = 0; i < 2; i++) {
                int r0 = row0 + wm * 32 + i * 16 + gq;
                bool ok0 = (r0 < M), ok1 = (r0 + 8 < M);
                float v0 = acc[i][n][0] + b0, v1 = acc[i][n][1] + b1;
                float v2 = acc[i][n][2] + b0, v3 = acc[i][n][3] + b1;
                if (ok0)
                    *reinterpret_cast<float2*>(C + (size_t)r0 * HID + col) = make_float2(v0, v1);
                if (ok1)
                    *reinterpret_cast<float2*>(C + (size_t)(r0 + 8) * HID + col) = make_float2(v2, v3);
                float a0 = ok0 ? v0 : 0.f, a1 = ok0 ? v1 : 0.f;
                float a2 = ok1 ? v2 : 0.f, a3 = ok1 ? v3 : 0.f;
                s0 += a0 + a2; s1 += a1 + a3;
                q0 += a0 * a0 + a2 * a2; q1 += a1 * a1 + a3 * a3;
            }
#pragma unroll
            for (int off = 4; off < 32; off <<= 1) {
                s0 += __shfl_xor_sync(0xffffffffu, s0, off);
                s1 += __shfl_xor_sync(0xffffffffu, s1, off);
                q0 += __shfl_xor_sync(0xffffffffu, q0, off);
                q1 += __shfl_xor_sync(0xffffffffu, q1, off);
            }
            if (lane < 4) {
                atomicAdd(&colsum[col], s0);
                atomicAdd(&colsum[col + 1], s1);
                atomicAdd(&colsq[col], q0);
                atomicAdd(&colsq[col + 1], q1);
            }
        }
    }
}

// ---------------- W transpose + split (once per launch) ----------------
__global__ void wsplit_kernel(const float* __restrict__ W1s,
                              const float* __restrict__ W2s) {
    __shared__ float tile[32][33];
    const int m = blockIdx.z;
    const float* W = (m & 1) ? (W2s + (size_t)(m >> 1) * HID * HID)
                             : (W1s + (size_t)(m >> 1) * HID * HID);
    const int kb = blockIdx.y * 32, nb = blockIdx.x * 32;
    const int tx = threadIdx.x, ty = threadIdx.y;
#pragma unroll
    for (int i = 0; i < 32; i += 8)
        tile[ty + i][tx] = W[(size_t)(kb + ty + i) * HID + nb + tx];
    __syncthreads();
#pragma unroll
    for (int i = 0; i < 32; i += 8) {
        int n = nb + ty + i, k = kb + tx;
        float v = tile[tx][ty + i];
        __nv_bfloat16 h = __float2bfloat16(v);
        float res = v - __bfloat162float(h);
        size_t o = (size_t)m * HID * HID + (size_t)n * HID + k;
        g_whi[o] = h;
        g_wlo[o] = __float2bfloat16(res);
    }
}

// ------- fused projection (blocks [0, PROJ_BLOCKS)) + edge degree count -------
#define PROJ_BLOCKS ((N_NODES + 31) / 32)
#define COUNT_BLOCKS ((N_EDGES + 255) / 256)
__global__ void __launch_bounds__(256) proj_count_kernel(const float* __restrict__ x,
                                                         const float* __restrict__ Wp,
                                                         const float* __restrict__ bp,
                                                         const int* __restrict__ dst) {
    const int tid = threadIdx.x;
    if (blockIdx.x >= PROJ_BLOCKS) {
        int e = (blockIdx.x - PROJ_BLOCKS) * 256 + tid;
        if (e < N_EDGES) atomicAdd(&g_deg[dst[e]], 1);
        return;
    }
    __shared__ float xs[32][IN_DIM];
    __shared__ float ws[IN_DIM * HID];
    for (int i = tid; i < IN_DIM * HID; i += 256) ws[i] = Wp[i];
    const int row0 = blockIdx.x * 32;
    for (int i = tid; i < 32 * IN_DIM; i += 256) {
        int r = i / IN_DIM, k = i % IN_DIM;
        xs[r][k] = (row0 + r < N_NODES) ? x[(row0 + r) * IN_DIM + k] : 0.f;
    }
    __syncthreads();
    float acc[32];
#pragma unroll
    for (int r = 0; r < 32; r++) acc[r] = 0.f;
    const int col = tid;
#pragma unroll
    for (int k = 0; k < IN_DIM; k++) {
        float w = ws[k * HID + col];
#pragma unroll
        for (int r = 0; r < 32; r++) acc[r] = fmaf(xs[r][k], w, acc[r]);
    }
    const float b = bp[col];
    for (int r = 0; r < 32; r++) {
        int rr = row0 + r;
        if (rr < N_NODES) g_h[rr * HID + col] = acc[r] + b;
    }
}

// ---------------- CSR scan + fill ----------------
__global__ void __launch_bounds__(1024) scan_kernel() {
    const int CH = (N_NODES + 1023) / 1024;
    const int tid = threadIdx.x;
    const int base = tid * CH;
    int s = 0;
    for (int i = 0; i < CH; i++) {
        int idx = base + i;
        if (idx < N_NODES) s += g_deg[idx];
    }
    __shared__ int bs[1024];
    bs[tid] = s;
    __syncthreads();
    for (int off = 1; off < 1024; off <<= 1) {
        int v = (tid >= off) ? bs[tid - off] : 0;
        __syncthreads();
        bs[tid] += v;
        __syncthreads();
    }
    int running = bs[tid] - s;
    for (int i = 0; i < CH; i++) {
        int idx = base + i;
        if (idx < N_NODES) {
            g_off[idx] = running;
            running += g_deg[idx];
            g_fill[idx] = 0;
        }
    }
    if (tid == 1023) g_off[N_NODES] = bs[1023];
}
__global__ void fill_kernel(const int* __restrict__ src, const int* __restrict__ dst) {
    int e = blockIdx.x * blockDim.x + threadIdx.x;
    if (e >= N_EDGES) return;
    int d = dst[e];
    int pos = g_off[d] + atomicAdd(&g_fill[d], 1);
    g_csr[pos] = src[e];
}

// ------- gather: zp[n] = pack((1+eps)*f(in[n]) + sum f(in[j])); zero deg+stats -------
template <bool BN>
__global__ void __launch_bounds__(256) gather_kernel(const float* __restrict__ eps, int l,
                                                     const float* __restrict__ gammas,
                                                     const float* __restrict__ betas) {
    const int tid = threadIdx.x;
    if (blockIdx.x == 0) {
        g_colsum2[l & 1][tid] = 0.f;
        g_colsq2[l & 1][tid] = 0.f;
    }
    {   // zero degree counters for next replay's count pass
        int zi = blockIdx.x * 256 + tid;
        if (blockIdx.x < (N_NODES + 255) / 256 && zi < N_NODES) g_deg[zi] = 0;
    }
    const int node = blockIdx.x * 4 + (tid >> 6);
    const int lane = tid & 63;
    if (node >= N_NODES) return;
    const float s = 1.f + eps[l];
    const int lo = g_off[node];
    const int hi = g_off[node + 1];
    const float4* in4 = reinterpret_cast<const float4*>(BN ? g_z : g_h);
    float4 sc, sh;
    if (BN) {
        const int pp = (l - 1) & 1;
        const float inv = 1.f / (float)N_NODES;
        float scv[4], shv[4];
#pragma unroll
        for (int j = 0; j < 4; j++) {
            int c = lane * 4 + j;
            float mu = g_colsum2[pp][c] * inv;
            float var = g_colsq2[pp][c] * inv - mu * mu;
            float rs = rsqrtf(var + BN_EPS);
            scv[j] = gammas[(l - 1) * HID + c] * rs;
            shv[j] = betas[(l - 1) * HID + c] - mu * scv[j];
        }
        sc = make_float4(scv[0], scv[1], scv[2], scv[3]);
        sh = make_float4(shv[0], shv[1], shv[2], shv[3]);
    }
    auto f = [&](float4 v) {
        if (BN) {
            v.x = fmaxf(fmaf(v.x, sc.x, sh.x), 0.f);
            v.y = fmaxf(fmaf(v.y, sc.y, sh.y), 0.f);
            v.z = fmaxf(fmaf(v.z, sc.z, sh.z), 0.f);
            v.w = fmaxf(fmaf(v.w, sc.w, sh.w), 0.f);
        }
        return v;
    };
    float4 a = f(in4[node * 64 + lane]);
    a.x *= s; a.y *= s; a.z *= s; a.w *= s;
    for (int i = lo; i < hi; i++) {
        int sr = g_csr[i];
        float4 v = f(in4[sr * 64 + lane]);
        a.x += v.x; a.y += v.y; a.z += v.z; a.w += v.w;
    }
    uint4 p;
    p.x = pack_split(a.x); p.y = pack_split(a.y);
    p.z = pack_split(a.z); p.w = pack_split(a.w);
    reinterpret_cast<uint4*>(g_zp)[node * 64 + lane] = p;
}

// ---------------- pooling with fused final BN+relu (stats parity 0) ----------------
__global__ void pool_kernel(const int* __restrict__ batch,
                            const float* __restrict__ gammas,
                            const float* __restrict__ betas) {
    const int g = blockIdx.x;
    const int col = threadIdx.x;
    __shared__ int s_lo, s_hi;
    if (col < 2) {
        int target = g + col;
        int lo = 0, hi = N_NODES;
        while (lo < hi) {
            int mid = (lo + hi) >> 1;
            if (batch[mid] < target) lo = mid + 1; else hi = mid;
        }
        if (col == 0) s_lo = lo; else s_hi = lo;
    }
    __syncthreads();
    const int lo = s_lo, hi = s_hi;
    const float inv = 1.f / (float)N_NODES;
    const float mu = g_colsum2[0][col] * inv;
    const float var = g_colsq2[0][col] * inv - mu * mu;
    const float rs = rsqrtf(var + BN_EPS);
    const float sc = gammas[(LAYERS - 1) * HID + col] * rs;
    const float sh = betas[(LAYERS - 1) * HID + col] - mu * sc;
    float s = 0.f;
    for (int r = lo; r < hi; r++)
        s += fmaxf(fmaf(g_z[r * HID + col], sc, sh), 0.f);
    g_pool[g * HID + col] = s / fmaxf((float)(hi - lo), 1.f);
}

// ---------------- readout SGEMM (fp32 SIMT, small M) ----------------
template <bool RELU>
__global__ void __launch_bounds__(256) sgemm_kernel(const float* __restrict__ A,
                                                    const float* __restrict__ B,
                                                    const float* __restrict__ bias,
                                                    float* __restrict__ C,
                                                    int M, int N, int K) {
    __shared__ float As[8][128];
    __shared__ float Bs[8][128];
    const int tid = threadIdx.x;
    const int row0 = blockIdx.x * 128;
    const int col0 = blockIdx.y * 128;
    const int tr = (tid >> 4) << 3;
    const int tc = (tid & 15) << 3;
    const int arow = tid >> 1;
    const int ak4 = (tid & 1) * 4;
    const int brow = tid >> 5;
    const int bcol = (tid & 31) * 4;
    float acc[8][8];
#pragma unroll
    for (int i = 0; i < 8; i++)
#pragma unroll
        for (int j = 0; j < 8; j++) acc[i][j] = 0.f;
    const int gar = row0 + arow;
    const bool arow_ok = (gar < M);
    for (int k0 = 0; k0 < K; k0 += 8) {
        float4 av = make_float4(0.f, 0.f, 0.f, 0.f);
        if (arow_ok)
            av = *reinterpret_cast<const float4*>(A + (size_t)gar * K + k0 + ak4);
        As[ak4 + 0][arow] = av.x;
        As[ak4 + 1][arow] = av.y;
        As[ak4 + 2][arow] = av.z;
        As[ak4 + 3][arow] = av.w;
        float4 bv = *reinterpret_cast<const float4*>(B + (size_t)(k0 + brow) * N + col0 + bcol);
        *reinterpret_cast<float4*>(&Bs[brow][bcol]) = bv;
        __syncthreads();
#pragma unroll
        for (int k = 0; k < 8; k++) {
            float ra[8], rb[8];
#pragma unroll
            for (int i = 0; i < 8; i++) ra[i] = As[k][tr + i];
#pragma unroll
            for (int j = 0; j < 8; j++) rb[j] = Bs[k][tc + j];
#pragma unroll
            for (int i = 0; i < 8; i++)
#pragma unroll
                for (int j = 0; j < 8; j++) acc[i][j] = fmaf(ra[i], rb[j], acc[i][j]);
        }
        __syncthreads();
    }
#pragma unroll
    for (int i = 0; i < 8; i++) {
        int r = row0 + tr + i;
        if (r >= M) break;
#pragma unroll
        for (int j = 0; j < 8; j += 4) {
            float4 v;
            v.x = acc[i][j + 0] + bias[col0 + tc + j + 0];
            v.y = acc[i][j + 1] + bias[col0 + tc + j + 1];
            v.z = acc[i][j + 2] + bias[col0 + tc + j + 2];
            v.w = acc[i][j + 3] + bias[col0 + tc + j + 3];
            if (RELU) {
                v.x = fmaxf(v.x, 0.f); v.y = fmaxf(v.y, 0.f);
                v.z = fmaxf(v.z, 0.f); v.w = fmaxf(v.w, 0.f);
            }
            *reinterpret_cast<float4*>(C + (size_t)r * N + col0 + tc + j) = v;
        }
    }
}

__global__ void readout2_kernel(const float* __restrict__ Wr2,
                                const float* __restrict__ br2,
                                float* __restrict__ out) {
    __shared__ float red[256];
    const int g = blockIdx.x;
    const int t = threadIdx.x;
    red[t] = g_r1[g * HID + t] * Wr2[t];
    __syncthreads();
    for (int s = 128; s > 0; s >>= 1) {
        if (t < s) red[t] += red[t + s];
        __syncthreads();
    }
    if (t == 0) out[g] = red[0] + br2[0];
}

// ---------------- host launcher ----------------
extern "C" void kernel_launch(void* const* d_in, const int* in_sizes, int n_in,
                              void* d_out, int out_size) {
    const float* x      = (const float*)d_in[0];
    const int*   ei     = (const int*)d_in[1];
    const int*   batch  = (const int*)d_in[2];
    const float* Wp     = (const float*)d_in[3];
    const float* bp     = (const float*)d_in[4];
    const float* eps    = (const float*)d_in[5];
    const float* W1s    = (const float*)d_in[6];
    const float* b1s    = (const float*)d_in[7];
    const float* W2s    = (const float*)d_in[8];
    const float* b2s    = (const float*)d_in[9];
    const float* gammas = (const float*)d_in[10];
    const float* betas  = (const float*)d_in[11];
    const float* Wr1    = (const float*)d_in[12];
    const float* br1    = (const float*)d_in[13];
    const float* Wr2    = (const float*)d_in[14];
    const float* br2    = (const float*)d_in[15];
    float* out = (float*)d_out;

    const int* src = ei;
    const int* dst = ei + N_EDGES;

    void *p_z, *p_zp, *p_tp, *p_pool, *p_r1, *p_whi, *p_wlo, *p_cs, *p_cq;
    cudaGetSymbolAddress(&p_z, g_z);
    cudaGetSymbolAddress(&p_zp, g_zp);
    cudaGetSymbolAddress(&p_tp, g_tp);
    cudaGetSymbolAddress(&p_pool, g_pool);
    cudaGetSymbolAddress(&p_r1, g_r1);
    cudaGetSymbolAddress(&p_whi, g_whi);
    cudaGetSymbolAddress(&p_wlo, g_wlo);
    cudaGetSymbolAddress(&p_cs, g_colsum2);
    cudaGetSymbolAddress(&p_cq, g_colsq2);
    float* dz = (float*)p_z;
    uint32_t* dzp = (uint32_t*)p_zp;
    uint32_t* dtp = (uint32_t*)p_tp;
    float* dpool = (float*)p_pool;
    float* dr1 = (float*)p_r1;
    __nv_bfloat16* dwhi = (__nv_bfloat16*)p_whi;
    __nv_bfloat16* dwlo = (__nv_bfloat16*)p_wlo;
    float* dcs = (float*)p_cs;
    float* dcq = (float*)p_cq;

    cudaFuncSetAttribute(gemm_mma_kernel<0>,
                         cudaFuncAttributeMaxDynamicSharedMemorySize, GEMM_SMEM);
    cudaFuncSetAttribute(gemm_mma_kernel<1>,
                         cudaFuncAttributeMaxDynamicSharedMemorySize, GEMM_SMEM);

    proj_count_kernel<<<PROJ_BLOCKS + COUNT_BLOCKS, 256>>>(x, Wp, bp, dst);
    scan_kernel<<<1, 1024>>>();
    fill_kernel<<<COUNT_BLOCKS, 256>>>(src, dst);

    const int ggrid = (N_NODES + 127) / 128;
    const size_t WSZ = (size_t)HID * HID;

    for (int l = 0; l < LAYERS; l++) {
        if (l == 0) {
            gather_kernel<false><<<(N_NODES + 3) / 4, 256>>>(eps, l, gammas, betas);
            wsplit_kernel<<<dim3(8, 8, 2 * LAYERS), dim3(32, 8)>>>(W1s, W2s);
        } else {
            gather_kernel<true><<<(N_NODES + 3) / 4, 256>>>(eps, l, gammas, betas);
        }
        gemm_mma_kernel<1><<<ggrid, 256, GEMM_SMEM>>>(
            dzp, dwhi + (2 * l) * WSZ, dwlo + (2 * l) * WSZ, b1s + l * HID,
            dtp, nullptr, nullptr, N_NODES);
        gemm_mma_kernel<0><<<ggrid, 256, GEMM_SMEM>>>(
            dtp, dwhi + (2 * l + 1) * WSZ, dwlo + (2 * l + 1) * WSZ, b2s + l * HID,
            dz, dcs + (l & 1) * HID, dcq + (l & 1) * HID, N_NODES);
    }

    pool_kernel<<<N_GRAPHS, 256>>>(batch, gammas, betas);

    const dim3 rgrid(N_GRAPHS / 128, HID / 128);
    sgemm_kernel<true><<<rgrid, 256>>>(dpool, Wr1, br1, dr1, N_GRAPHS, HID, HID);
    readout2_kernel<<<N_GRAPHS, 256>>>(Wr2, br2, out);
}

// round 8
// speedup vs baseline: 1.3601x; 1.3601x over previous
#include <cuda_runtime.h>
#include <cuda_fp16.h>
#include <cuda_bf16.h>
#include <cstdint>

#define N_NODES 100000
#define N_EDGES 300000
#define N_GRAPHS 2048
#define IN_DIM 38
#define HID 256
#define LAYERS 5
#define BN_EPS 1e-5f

// ---------------- device scratch ----------------
__device__ float g_h[N_NODES * HID];          // fp32 features (proj out)
__device__ float g_z[N_NODES * HID];          // GEMM2 output (pre-BN)
__device__ __half g_zp[N_NODES * HID];        // fp16 GEMM1 input
__device__ __half g_tp[N_NODES * HID];        // fp16 GEMM1 out / GEMM2 in
__device__ __half g_whi[2 * LAYERS * HID * HID];  // W^T hi, [mat][n][k]
__device__ __half g_wlo[2 * LAYERS * HID * HID];  // W^T lo (fp16 residual)
__device__ float g_colsum2[2][HID];
__device__ float g_colsq2[2][HID];
__device__ float g_pool[N_GRAPHS * HID];
__device__ float g_r1[N_GRAPHS * HID];
__device__ int g_deg[N_NODES];
__device__ int g_fill[N_NODES];
__device__ int g_off[N_NODES + 1];
__device__ int g_csr[N_EDGES];

__device__ __forceinline__ uint32_t smem_u32(const void* p) {
    uint32_t a;
    asm("{ .reg .u64 t; cvta.to.shared.u64 t, %1; cvt.u32.u64 %0, t; }"
        : "=r"(a) : "l"(p));
    return a;
}

__device__ __forceinline__ uint32_t pack_h2(float x, float y) {
    __half2 h = __floats2half2_rn(x, y);
    return *reinterpret_cast<uint32_t*>(&h);
}

#define MMA_F16(c, a0, a1, a2, a3, b0, b1)                                     \
    asm volatile(                                                              \
        "mma.sync.aligned.m16n8k16.row.col.f32.f16.f16.f32 "                   \
        "{%0,%1,%2,%3}, {%4,%5,%6,%7}, {%8,%9}, {%0,%1,%2,%3};"                \
        : "+f"((c)[0]), "+f"((c)[1]), "+f"((c)[2]), "+f"((c)[3])               \
        : "r"(a0), "r"(a1), "r"(a2), "r"(a3), "r"(b0), "r"(b1))

#define CP_ASYNC16(dst, src) \
    asm volatile("cp.async.ca.shared.global [%0], [%1], 16;" \
                 :: "r"(dst), "l"(src) : "memory")
#define CP_ASYNC16_Z(dst, src, n) \
    asm volatile("cp.async.ca.shared.global [%0], [%1], 16, %2;" \
                 :: "r"(dst), "l"(src), "r"(n) : "memory")
#define CP_COMMIT() asm volatile("cp.async.commit_group;" ::: "memory")

// stage: A fp16 128 rows x 80B (64B data + 16B pad) = 10240B; BH/BL 128 x 80B
#define STG 30720
#define A_ST(s)  ((s) * STG)
#define BH_ST(s) ((s) * STG + 10240)
#define BL_ST(s) ((s) * STG + 20480)
#define GEMM_SMEM (2 * STG)

// ====== GEMM: C[M,256] = A_f16 @ (Whi+Wlo)[n][k]^T + bias (2-term fp16 split) ======
// OUTMODE 0: fp32 out + fused stats; OUTMODE 1: relu + fp16 out.
template <int OUTMODE>
__global__ void __launch_bounds__(256, 2)
gemm_mma_kernel(const __half* __restrict__ Ap,
                const __half* __restrict__ Whi,
                const __half* __restrict__ Wlo,
                const float* __restrict__ bias,
                void* __restrict__ Cout,
                float* __restrict__ colsum, float* __restrict__ colsq, int M) {
    extern __shared__ char sm[];
    const uint32_t smb = smem_u32(sm);
    const int tid = threadIdx.x;
    const int lane = tid & 31;
    const int wid = tid >> 5;
    const int wm = wid & 3;
    const int wn = wid >> 2;
    const int gq = lane >> 2;
    const int tq = lane & 3;
    const int row0 = blockIdx.x * 128;
    const int col0 = blockIdx.y * 128;

    float acc[2][8][4];
#pragma unroll
    for (int i = 0; i < 2; i++)
#pragma unroll
        for (int n = 0; n < 8; n++)
#pragma unroll
            for (int q = 0; q < 4; q++) acc[i][n][q] = 0.f;

    auto load_chunk = [&](int c, int s) {
        const int k0 = c * 32;
        // A: 128 rows x 64B fp16
#pragma unroll
        for (int i = 0; i < 2; i++) {
            int idx = tid + 256 * i;
            int r = idx >> 2, q = idx & 3;
            int gr = row0 + r;
            int nb = (gr < M) ? 16 : 0;
            int grc = (gr < M) ? gr : (M - 1);
            const char* src = (const char*)(Ap + (size_t)grc * HID + k0 + q * 8);
            CP_ASYNC16_Z(smb + A_ST(s) + r * 80 + q * 16, src, nb);
        }
        // B hi/lo: 128 n-rows x 64B each
#pragma unroll
        for (int i = 0; i < 4; i++) {
            int idx = tid + 256 * i;
            int half_ = idx >> 9, i2 = idx & 511;
            int r = i2 >> 2, q = i2 & 3;
            const __half* W = half_ ? Wlo : Whi;
            const char* src = (const char*)(W + (size_t)(col0 + r) * HID + k0 + q * 8);
            uint32_t dst = smb + (half_ ? BL_ST(s) : BH_ST(s)) + r * 80 + q * 16;
            CP_ASYNC16(dst, src);
        }
        CP_COMMIT();
    };

    auto compute = [&](int s) {
#pragma unroll
        for (int j = 0; j < 2; j++) {
            uint32_t a[2][4];
#pragma unroll
            for (int i = 0; i < 2; i++) {
                int rb = wm * 32 + i * 16;
                const char* pA = sm + A_ST(s);
                a[i][0] = *reinterpret_cast<const uint32_t*>(pA + (rb + gq) * 80 + j * 32 + tq * 4);
                a[i][1] = *reinterpret_cast<const uint32_t*>(pA + (rb + 8 + gq) * 80 + j * 32 + tq * 4);
                a[i][2] = *reinterpret_cast<const uint32_t*>(pA + (rb + gq) * 80 + j * 32 + tq * 4 + 16);
                a[i][3] = *reinterpret_cast<const uint32_t*>(pA + (rb + 8 + gq) * 80 + j * 32 + tq * 4 + 16);
            }
#pragma unroll
            for (int n = 0; n < 8; n++) {
                int cb = wn * 64 + n * 8 + gq;
                uint32_t bh0 = *reinterpret_cast<const uint32_t*>(sm + BH_ST(s) + cb * 80 + j * 32 + tq * 4);
                uint32_t bh1 = *reinterpret_cast<const uint32_t*>(sm + BH_ST(s) + cb * 80 + j * 32 + tq * 4 + 16);
                uint32_t bl0 = *reinterpret_cast<const uint32_t*>(sm + BL_ST(s) + cb * 80 + j * 32 + tq * 4);
                uint32_t bl1 = *reinterpret_cast<const uint32_t*>(sm + BL_ST(s) + cb * 80 + j * 32 + tq * 4 + 16);
                MMA_F16(acc[0][n], a[0][0], a[0][1], a[0][2], a[0][3], bh0, bh1);
                MMA_F16(acc[1][n], a[1][0], a[1][1], a[1][2], a[1][3], bh0, bh1);
                MMA_F16(acc[0][n], a[0][0], a[0][1], a[0][2], a[0][3], bl0, bl1);
                MMA_F16(acc[1][n], a[1][0], a[1][1], a[1][2], a[1][3], bl0, bl1);
            }
        }
    };

    load_chunk(0, 0);
    load_chunk(1, 1);

#pragma unroll 1
    for (int c = 0; c < 8; c++) {
        if (c < 6) asm volatile("cp.async.wait_group 1;" ::: "memory");
        else       asm volatile("cp.async.wait_group 0;" ::: "memory");
        __syncthreads();
        compute(c & 1);
        __syncthreads();
        if (c + 2 < 8) load_chunk(c + 2, c & 1);
    }

    // ---------------- epilogue ----------------
    if (OUTMODE == 1) {
        uint32_t* C = (uint32_t*)Cout;   // fp16 pairs
#pragma unroll
        for (int i = 0; i < 2; i++) {
            int r0 = row0 + wm * 32 + i * 16 + gq;
#pragma unroll
            for (int n = 0; n < 8; n++) {
                int col = col0 + wn * 64 + n * 8 + tq * 2;
                float b0 = bias[col], b1 = bias[col + 1];
                float v0 = fmaxf(acc[i][n][0] + b0, 0.f);
                float v1 = fmaxf(acc[i][n][1] + b1, 0.f);
                float v2 = fmaxf(acc[i][n][2] + b0, 0.f);
                float v3 = fmaxf(acc[i][n][3] + b1, 0.f);
                if (r0 < M)
                    C[(size_t)r0 * (HID / 2) + (col >> 1)] = pack_h2(v0, v1);
                if (r0 + 8 < M)
                    C[(size_t)(r0 + 8) * (HID / 2) + (col >> 1)] = pack_h2(v2, v3);
            }
        }
    } else {
        float s[16], q[16];
#pragma unroll
        for (int k = 0; k < 16; k++) { s[k] = 0.f; q[k] = 0.f; }
#pragma unroll
        for (int i = 0; i < 2; i++) {
            int r0 = row0 + wm * 32 + i * 16 + gq;
            bool ok0 = (r0 < M), ok1 = (r0 + 8 < M);
#pragma unroll
            for (int n = 0; n < 8; n++) {
                int col = col0 + wn * 64 + n * 8 + tq * 2;
                float b0 = bias[col], b1 = bias[col + 1];
                float v0 = acc[i][n][0] + b0, v1 = acc[i][n][1] + b1;
                float v2 = acc[i][n][2] + b0, v3 = acc[i][n][3] + b1;
                float* C = (float*)Cout;
                if (ok0)
                    *reinterpret_cast<float2*>(C + (size_t)r0 * HID + col) = make_float2(v0, v1);
                if (ok1)
                    *reinterpret_cast<float2*>(C + (size_t)(r0 + 8) * HID + col) = make_float2(v2, v3);
                float a0 = ok0 ? v0 : 0.f, a1 = ok0 ? v1 : 0.f;
                float a2 = ok1 ? v2 : 0.f, a3 = ok1 ? v3 : 0.f;
                s[n * 2 + 0] += a0 + a2;
                s[n * 2 + 1] += a1 + a3;
                q[n * 2 + 0] += a0 * a0 + a2 * a2;
                q[n * 2 + 1] += a1 * a1 + a3 * a3;
            }
        }
#pragma unroll
        for (int k = 0; k < 16; k++) {
#pragma unroll
            for (int off = 4; off < 32; off <<= 1) {
                s[k] += __shfl_xor_sync(0xffffffffu, s[k], off);
                q[k] += __shfl_xor_sync(0xffffffffu, q[k], off);
            }
        }
        if (lane < 4) {
#pragma unroll
            for (int k = 0; k < 16; k++) {
                int col = col0 + wn * 64 + (k >> 1) * 8 + lane * 2 + (k & 1);
                atomicAdd(&colsum[col], s[k]);
                atomicAdd(&colsq[col], q[k]);
            }
        }
    }
}

// ---------------- W transpose + split (once per launch) ----------------
__global__ void wsplit_kernel(const float* __restrict__ W1s,
                              const float* __restrict__ W2s) {
    __shared__ float tile[32][33];
    const int m = blockIdx.z;
    const float* W = (m & 1) ? (W2s + (size_t)(m >> 1) * HID * HID)
                             : (W1s + (size_t)(m >> 1) * HID * HID);
    const int kb = blockIdx.y * 32, nb = blockIdx.x * 32;
    const int tx = threadIdx.x, ty = threadIdx.y;
#pragma unroll
    for (int i = 0; i < 32; i += 8)
        tile[ty + i][tx] = W[(size_t)(kb + ty + i) * HID + nb + tx];
    __syncthreads();
#pragma unroll
    for (int i = 0; i < 32; i += 8) {
        int n = nb + ty + i, k = kb + tx;
        float v = tile[tx][ty + i];
        __half h = __float2half(v);
        float res = v - __half2float(h);
        size_t o = (size_t)m * HID * HID + (size_t)n * HID + k;
        g_whi[o] = h;
        g_wlo[o] = __float2half(res);
    }
}

// ---------------- projection: h = x @ Wp + bp ----------------
__global__ void __launch_bounds__(256) proj_kernel(const float* __restrict__ x,
                                                   const float* __restrict__ Wp,
                                                   const float* __restrict__ bp) {
    __shared__ float xs[32][IN_DIM];
    __shared__ float ws[IN_DIM * HID];
    const int tid = threadIdx.x;
    for (int i = tid; i < IN_DIM * HID; i += 256) ws[i] = Wp[i];
    const int row0 = blockIdx.x * 32;
    for (int i = tid; i < 32 * IN_DIM; i += 256) {
        int r = i / IN_DIM, k = i % IN_DIM;
        xs[r][k] = (row0 + r < N_NODES) ? x[(row0 + r) * IN_DIM + k] : 0.f;
    }
    __syncthreads();
    float acc[32];
#pragma unroll
    for (int r = 0; r < 32; r++) acc[r] = 0.f;
    const int col = tid;
#pragma unroll
    for (int k = 0; k < IN_DIM; k++) {
        float w = ws[k * HID + col];
#pragma unroll
        for (int r = 0; r < 32; r++) acc[r] = fmaf(xs[r][k], w, acc[r]);
    }
    const float b = bp[col];
    for (int r = 0; r < 32; r++) {
        int rr = row0 + r;
        if (rr < N_NODES) g_h[rr * HID + col] = acc[r] + b;
    }
}

// ---------------- CSR build ----------------
__global__ void zero_deg_kernel() {
    int i = blockIdx.x * blockDim.x + threadIdx.x;
    if (i < N_NODES) g_deg[i] = 0;
}
__global__ void count_kernel(const int* __restrict__ dst) {
    int e = blockIdx.x * blockDim.x + threadIdx.x;
    if (e < N_EDGES) atomicAdd(&g_deg[dst[e]], 1);
}
__global__ void __launch_bounds__(1024) scan_kernel() {
    const int CH = (N_NODES + 1023) / 1024;
    const int tid = threadIdx.x;
    const int base = tid * CH;
    int s = 0;
    for (int i = 0; i < CH; i++) {
        int idx = base + i;
        if (idx < N_NODES) s += g_deg[idx];
    }
    __shared__ int bs[1024];
    bs[tid] = s;
    __syncthreads();
    for (int off = 1; off < 1024; off <<= 1) {
        int v = (tid >= off) ? bs[tid - off] : 0;
        __syncthreads();
        bs[tid] += v;
        __syncthreads();
    }
    int running = bs[tid] - s;
    for (int i = 0; i < CH; i++) {
        int idx = base + i;
        if (idx < N_NODES) {
            g_off[idx] = running;
            running += g_deg[idx];
            g_fill[idx] = 0;
        }
    }
    if (tid == 1023) g_off[N_NODES] = bs[1023];
}
__global__ void fill_kernel(const int* __restrict__ src, const int* __restrict__ dst) {
    int e = blockIdx.x * blockDim.x + threadIdx.x;
    if (e >= N_EDGES) return;
    int d = dst[e];
    int pos = g_off[d] + atomicAdd(&g_fill[d], 1);
    g_csr[pos] = src[e];
}

// ------- gather: zp[n] = fp16((1+eps)*f(in[n]) + sum f(in[j])); zero stats -------
template <bool BN>
__global__ void __launch_bounds__(256) gather_kernel(const float* __restrict__ eps, int l,
                                                     const float* __restrict__ gammas,
                                                     const float* __restrict__ betas) {
    const int tid = threadIdx.x;
    if (blockIdx.x == 0) {
        g_colsum2[l & 1][tid] = 0.f;
        g_colsq2[l & 1][tid] = 0.f;
    }
    const int node = blockIdx.x * 4 + (tid >> 6);
    const int lane = tid & 63;
    if (node >= N_NODES) return;
    const float s = 1.f + eps[l];
    const int lo = g_off[node];
    const int hi = g_off[node + 1];
    const float4* in4 = reinterpret_cast<const float4*>(BN ? g_z : g_h);
    float4 sc, sh;
    if (BN) {
        const int pp = (l - 1) & 1;
        const float inv = 1.f / (float)N_NODES;
        float scv[4], shv[4];
#pragma unroll
        for (int j = 0; j < 4; j++) {
            int c = lane * 4 + j;
            float mu = g_colsum2[pp][c] * inv;
            float var = g_colsq2[pp][c] * inv - mu * mu;
            float rs = rsqrtf(var + BN_EPS);
            scv[j] = gammas[(l - 1) * HID + c] * rs;
            shv[j] = betas[(l - 1) * HID + c] - mu * scv[j];
        }
        sc = make_float4(scv[0], scv[1], scv[2], scv[3]);
        sh = make_float4(shv[0], shv[1], shv[2], shv[3]);
    }
    auto f = [&](float4 v) {
        if (BN) {
            v.x = fmaxf(fmaf(v.x, sc.x, sh.x), 0.f);
            v.y = fmaxf(fmaf(v.y, sc.y, sh.y), 0.f);
            v.z = fmaxf(fmaf(v.z, sc.z, sh.z), 0.f);
            v.w = fmaxf(fmaf(v.w, sc.w, sh.w), 0.f);
        }
        return v;
    };
    float4 a = f(in4[node * 64 + lane]);
    a.x *= s; a.y *= s; a.z *= s; a.w *= s;
    for (int i = lo; i < hi; i++) {
        int sr = g_csr[i];
        float4 v = f(in4[sr * 64 + lane]);
        a.x += v.x; a.y += v.y; a.z += v.z; a.w += v.w;
    }
    uint2 p;
    p.x = pack_h2(a.x, a.y);
    p.y = pack_h2(a.z, a.w);
    reinterpret_cast<uint2*>(g_zp)[node * 64 + lane] = p;
}

// ---------------- pooling with fused final BN+relu (stats parity 0) ----------------
__global__ void pool_kernel(const int* __restrict__ batch,
                            const float* __restrict__ gammas,
                            const float* __restrict__ betas) {
    const int g = blockIdx.x;
    const int col = threadIdx.x;
    __shared__ int s_lo, s_hi;
    if (col < 2) {
        int target = g + col;
        int lo = 0, hi = N_NODES;
        while (lo < hi) {
            int mid = (lo + hi) >> 1;
            if (batch[mid] < target) lo = mid + 1; else hi = mid;
        }
        if (col == 0) s_lo = lo; else s_hi = lo;
    }
    __syncthreads();
    const int lo = s_lo, hi = s_hi;
    const float inv = 1.f / (float)N_NODES;
    const float mu = g_colsum2[0][col] * inv;
    const float var = g_colsq2[0][col] * inv - mu * mu;
    const float rs = rsqrtf(var + BN_EPS);
    const float sc = gammas[(LAYERS - 1) * HID + col] * rs;
    const float sh = betas[(LAYERS - 1) * HID + col] - mu * sc;
    float s = 0.f;
    for (int r = lo; r < hi; r++)
        s += fmaxf(fmaf(g_z[r * HID + col], sc, sh), 0.f);
    g_pool[g * HID + col] = s / fmaxf((float)(hi - lo), 1.f);
}

// ---------------- readout SGEMM (fp32 SIMT, small M) ----------------
template <bool RELU>
__global__ void __launch_bounds__(256) sgemm_kernel(const float* __restrict__ A,
                                                    const float* __restrict__ B,
                                                    const float* __restrict__ bias,
                                                    float* __restrict__ C,
                                                    int M, int N, int K) {
    __shared__ float As[8][128];
    __shared__ float Bs[8][128];
    const int tid = threadIdx.x;
    const int row0 = blockIdx.x * 128;
    const int col0 = blockIdx.y * 128;
    const int tr = (tid >> 4) << 3;
    const int tc = (tid & 15) << 3;
    const int arow = tid >> 1;
    const int ak4 = (tid & 1) * 4;
    const int brow = tid >> 5;
    const int bcol = (tid & 31) * 4;
    float acc[8][8];
#pragma unroll
    for (int i = 0; i < 8; i++)
#pragma unroll
        for (int j = 0; j < 8; j++) acc[i][j] = 0.f;
    const int gar = row0 + arow;
    const bool arow_ok = (gar < M);
    for (int k0 = 0; k0 < K; k0 += 8) {
        float4 av = make_float4(0.f, 0.f, 0.f, 0.f);
        if (arow_ok)
            av = *reinterpret_cast<const float4*>(A + (size_t)gar * K + k0 + ak4);
        As[ak4 + 0][arow] = av.x;
        As[ak4 + 1][arow] = av.y;
        As[ak4 + 2][arow] = av.z;
        As[ak4 + 3][arow] = av.w;
        float4 bv = *reinterpret_cast<const float4*>(B + (size_t)(k0 + brow) * N + col0 + bcol);
        *reinterpret_cast<float4*>(&Bs[brow][bcol]) = bv;
        __syncthreads();
#pragma unroll
        for (int k = 0; k < 8; k++) {
            float ra[8], rb[8];
#pragma unroll
            for (int i = 0; i < 8; i++) ra[i] = As[k][tr + i];
#pragma unroll
            for (int j = 0; j < 8; j++) rb[j] = Bs[k][tc + j];
#pragma unroll
            for (int i = 0; i < 8; i++)
#pragma unroll
                for (int j = 0; j < 8; j++) acc[i][j] = fmaf(ra[i], rb[j], acc[i][j]);
        }
        __syncthreads();
    }
#pragma unroll
    for (int i = 0; i < 8; i++) {
        int r = row0 + tr + i;
        if (r >= M) break;
#pragma unroll
        for (int j = 0; j < 8; j += 4) {
            float4 v;
            v.x = acc[i][j + 0] + bias[col0 + tc + j + 0];
            v.y = acc[i][j + 1] + bias[col0 + tc + j + 1];
            v.z = acc[i][j + 2] + bias[col0 + tc + j + 2];
            v.w = acc[i][j + 3] + bias[col0 + tc + j + 3];
            if (RELU) {
                v.x = fmaxf(v.x, 0.f); v.y = fmaxf(v.y, 0.f);
                v.z = fmaxf(v.z, 0.f); v.w = fmaxf(v.w, 0.f);
            }
            *reinterpret_cast<float4*>(C + (size_t)r * N + col0 + tc + j) = v;
        }
    }
}

__global__ void readout2_kernel(const float* __restrict__ Wr2,
                                const float* __restrict__ br2,
                                float* __restrict__ out) {
    __shared__ float red[256];
    const int g = blockIdx.x;
    const int t = threadIdx.x;
    red[t] = g_r1[g * HID + t] * Wr2[t];
    __syncthreads();
    for (int s = 128; s > 0; s >>= 1) {
        if (t < s) red[t] += red[t + s];
        __syncthreads();
    }
    if (t == 0) out[g] = red[0] + br2[0];
}

// ---------------- host launcher ----------------
extern "C" void kernel_launch(void* const* d_in, const int* in_sizes, int n_in,
                              void* d_out, int out_size) {
    const float* x      = (const float*)d_in[0];
    const int*   ei     = (const int*)d_in[1];
    const int*   batch  = (const int*)d_in[2];
    const float* Wp     = (const float*)d_in[3];
    const float* bp     = (const float*)d_in[4];
    const float* eps    = (const float*)d_in[5];
    const float* W1s    = (const float*)d_in[6];
    const float* b1s    = (const float*)d_in[7];
    const float* W2s    = (const float*)d_in[8];
    const float* b2s    = (const float*)d_in[9];
    const float* gammas = (const float*)d_in[10];
    const float* betas  = (const float*)d_in[11];
    const float* Wr1    = (const float*)d_in[12];
    const float* br1    = (const float*)d_in[13];
    const float* Wr2    = (const float*)d_in[14];
    const float* br2    = (const float*)d_in[15];
    float* out = (float*)d_out;

    const int* src = ei;
    const int* dst = ei + N_EDGES;

    void *p_z, *p_zp, *p_tp, *p_pool, *p_r1, *p_whi, *p_wlo, *p_cs, *p_cq;
    cudaGetSymbolAddress(&p_z, g_z);
    cudaGetSymbolAddress(&p_zp, g_zp);
    cudaGetSymbolAddress(&p_tp, g_tp);
    cudaGetSymbolAddress(&p_pool, g_pool);
    cudaGetSymbolAddress(&p_r1, g_r1);
    cudaGetSymbolAddress(&p_whi, g_whi);
    cudaGetSymbolAddress(&p_wlo, g_wlo);
    cudaGetSymbolAddress(&p_cs, g_colsum2);
    cudaGetSymbolAddress(&p_cq, g_colsq2);
    float* dz = (float*)p_z;
    __half* dzp = (__half*)p_zp;
    __half* dtp = (__half*)p_tp;
    float* dpool = (float*)p_pool;
    float* dr1 = (float*)p_r1;
    __half* dwhi = (__half*)p_whi;
    __half* dwlo = (__half*)p_wlo;
    float* dcs = (float*)p_cs;
    float* dcq = (float*)p_cq;

    cudaFuncSetAttribute(gemm_mma_kernel<0>,
                         cudaFuncAttributeMaxDynamicSharedMemorySize, GEMM_SMEM);
    cudaFuncSetAttribute(gemm_mma_kernel<1>,
                         cudaFuncAttributeMaxDynamicSharedMemorySize, GEMM_SMEM);

    // CSR build + W split + projection
    zero_deg_kernel<<<(N_NODES + 255) / 256, 256>>>();
    count_kernel<<<(N_EDGES + 255) / 256, 256>>>(dst);
    scan_kernel<<<1, 1024>>>();
    fill_kernel<<<(N_EDGES + 255) / 256, 256>>>(src, dst);
    wsplit_kernel<<<dim3(8, 8, 2 * LAYERS), dim3(32, 8)>>>(W1s, W2s);
    proj_kernel<<<(N_NODES + 31) / 32, 256>>>(x, Wp, bp);

    const dim3 ggrid((N_NODES + 127) / 128, 2);
    const size_t WSZ = (size_t)HID * HID;

    for (int l = 0; l < LAYERS; l++) {
        if (l == 0)
            gather_kernel<false><<<(N_NODES + 3) / 4, 256>>>(eps, l, gammas, betas);
        else
            gather_kernel<true><<<(N_NODES + 3) / 4, 256>>>(eps, l, gammas, betas);
        gemm_mma_kernel<1><<<ggrid, 256, GEMM_SMEM>>>(
            dzp, dwhi + (2 * l) * WSZ, dwlo + (2 * l) * WSZ, b1s + l * HID,
            dtp, nullptr, nullptr, N_NODES);
        gemm_mma_kernel<0><<<ggrid, 256, GEMM_SMEM>>>(
            dtp, dwhi + (2 * l + 1) * WSZ, dwlo + (2 * l + 1) * WSZ, b2s + l * HID,
            dz, dcs + (l & 1) * HID, dcq + (l & 1) * HID, N_NODES);
    }

    pool_kernel<<<N_GRAPHS, 256>>>(batch, gammas, betas);

    const dim3 rgrid(N_GRAPHS / 128, HID / 128);
    sgemm_kernel<true><<<rgrid, 256>>>(dpool, Wr1, br1, dr1, N_GRAPHS, HID, HID);
    readout2_kernel<<<N_GRAPHS, 256>>>(Wr2, br2, out);
}

// round 9
// speedup vs baseline: 1.4094x; 1.0363x over previous
#include <cuda_runtime.h>
#include <cuda_fp16.h>
#include <cuda_bf16.h>
#include <cstdint>

#define N_NODES 100000
#define N_EDGES 300000
#define N_GRAPHS 2048
#define IN_DIM 38
#define HID 256
#define LAYERS 5
#define BN_EPS 1e-5f

// ---------------- device scratch ----------------
__device__ float g_h[N_NODES * HID];          // fp32 features (proj out)
__device__ float g_z[N_NODES * HID];          // GEMM2 output (pre-BN)
__device__ __half g_zp[N_NODES * HID];        // fp16 GEMM1 input
__device__ __half g_tp[N_NODES * HID];        // fp16 GEMM1 out / GEMM2 in
__device__ __half g_whi[2 * LAYERS * HID * HID];  // W^T hi, [mat][n][k]
__device__ __half g_wlo[2 * LAYERS * HID * HID];  // W^T lo (fp16 residual)
__device__ float g_colsum2[2][HID];
__device__ float g_colsq2[2][HID];
__device__ float g_pool[N_GRAPHS * HID];
__device__ float g_r1[N_GRAPHS * HID];
__device__ int g_deg[N_NODES];
__device__ int g_fill[N_NODES];
__device__ int g_off[N_NODES + 1];
__device__ int g_csr[N_EDGES];

__device__ __forceinline__ uint32_t smem_u32(const void* p) {
    uint32_t a;
    asm("{ .reg .u64 t; cvta.to.shared.u64 t, %1; cvt.u32.u64 %0, t; }"
        : "=r"(a) : "l"(p));
    return a;
}

__device__ __forceinline__ uint32_t pack_h2(float x, float y) {
    __half2 h = __floats2half2_rn(x, y);
    return *reinterpret_cast<uint32_t*>(&h);
}

#define MMA_F16(c, a0, a1, a2, a3, b0, b1)                                     \
    asm volatile(                                                              \
        "mma.sync.aligned.m16n8k16.row.col.f32.f16.f16.f32 "                   \
        "{%0,%1,%2,%3}, {%4,%5,%6,%7}, {%8,%9}, {%0,%1,%2,%3};"                \
        : "+f"((c)[0]), "+f"((c)[1]), "+f"((c)[2]), "+f"((c)[3])               \
        : "r"(a0), "r"(a1), "r"(a2), "r"(a3), "r"(b0), "r"(b1))

#define LDMX4(r, addr)                                                         \
    asm volatile("ldmatrix.sync.aligned.m8n8.x4.shared.b16 {%0,%1,%2,%3}, [%4];" \
        : "=r"((r)[0]), "=r"((r)[1]), "=r"((r)[2]), "=r"((r)[3]) : "r"(addr))

#define CP_ASYNC16(dst, src) \
    asm volatile("cp.async.ca.shared.global [%0], [%1], 16;" \
                 :: "r"(dst), "l"(src) : "memory")
#define CP_ASYNC16_Z(dst, src, n) \
    asm volatile("cp.async.ca.shared.global [%0], [%1], 16, %2;" \
                 :: "r"(dst), "l"(src), "r"(n) : "memory")
#define CP_COMMIT() asm volatile("cp.async.commit_group;" ::: "memory")

// stage: A fp16 128 rows x 80B (64B data + 16B pad) = 10240B; BH/BL 128 x 80B
#define STG 30720
#define A_ST(s)  ((s) * STG)
#define BH_ST(s) ((s) * STG + 10240)
#define BL_ST(s) ((s) * STG + 20480)
#define GEMM_SMEM (2 * STG)

// ====== GEMM: C[M,256] = A_f16 @ (Whi+Wlo)[n][k]^T + bias (2-term fp16 split) ======
// OUTMODE 0: fp32 out + fused stats; OUTMODE 1: relu + fp16 out.
template <int OUTMODE>
__global__ void __launch_bounds__(256, 2)
gemm_mma_kernel(const __half* __restrict__ Ap,
                const __half* __restrict__ Whi,
                const __half* __restrict__ Wlo,
                const float* __restrict__ bias,
                void* __restrict__ Cout,
                float* __restrict__ colsum, float* __restrict__ colsq, int M) {
    extern __shared__ char sm[];
    const uint32_t smb = smem_u32(sm);
    const int tid = threadIdx.x;
    const int lane = tid & 31;
    const int wid = tid >> 5;
    const int wm = wid & 3;
    const int wn = wid >> 2;
    const int gq = lane >> 2;
    const int tq = lane & 3;
    const int row0 = blockIdx.x * 128;
    const int col0 = blockIdx.y * 128;

    float acc[2][8][4];
#pragma unroll
    for (int i = 0; i < 2; i++)
#pragma unroll
        for (int n = 0; n < 8; n++)
#pragma unroll
            for (int q = 0; q < 4; q++) acc[i][n][q] = 0.f;

    auto load_chunk = [&](int c, int s) {
        const int k0 = c * 32;
        // A: 128 rows x 64B fp16
#pragma unroll
        for (int i = 0; i < 2; i++) {
            int idx = tid + 256 * i;
            int r = idx >> 2, q = idx & 3;
            int gr = row0 + r;
            int nb = (gr < M) ? 16 : 0;
            int grc = (gr < M) ? gr : (M - 1);
            const char* src = (const char*)(Ap + (size_t)grc * HID + k0 + q * 8);
            CP_ASYNC16_Z(smb + A_ST(s) + r * 80 + q * 16, src, nb);
        }
        // B hi/lo: 128 n-rows x 64B each
#pragma unroll
        for (int i = 0; i < 4; i++) {
            int idx = tid + 256 * i;
            int half_ = idx >> 9, i2 = idx & 511;
            int r = i2 >> 2, q = i2 & 3;
            const __half* W = half_ ? Wlo : Whi;
            const char* src = (const char*)(W + (size_t)(col0 + r) * HID + k0 + q * 8);
            uint32_t dst = smb + (half_ ? BL_ST(s) : BH_ST(s)) + r * 80 + q * 16;
            CP_ASYNC16(dst, src);
        }
        CP_COMMIT();
    };

    // ldmatrix lane mappings
    const int a_lrow = lane & 15;               // row within 16-row A block
    const int a_koff = (lane >> 4) * 16;        // k halves (bytes)
    const int b_lrow = ((lane & 16) >> 1) + (lane & 7);  // n rows for 2 groups
    const int b_koff = ((lane >> 3) & 1) * 16;           // k halves (bytes)

    auto compute = [&](int s) {
#pragma unroll
        for (int j = 0; j < 2; j++) {
            uint32_t a[2][4];
#pragma unroll
            for (int i = 0; i < 2; i++) {
                uint32_t ro = (uint32_t)(wm * 32 + i * 16 + a_lrow) * 80 + j * 32 + a_koff;
                LDMX4(a[i], smb + A_ST(s) + ro);
            }
#pragma unroll
            for (int np = 0; np < 4; np++) {
                uint32_t bh[4], bl[4];
                uint32_t bo = (uint32_t)(wn * 64 + np * 16 + b_lrow) * 80 + j * 32 + b_koff;
                LDMX4(bh, smb + BH_ST(s) + bo);
                LDMX4(bl, smb + BL_ST(s) + bo);
#pragma unroll
                for (int i = 0; i < 2; i++) {
                    MMA_F16(acc[i][np * 2],     a[i][0], a[i][1], a[i][2], a[i][3], bh[0], bh[1]);
                    MMA_F16(acc[i][np * 2],     a[i][0], a[i][1], a[i][2], a[i][3], bl[0], bl[1]);
                    MMA_F16(acc[i][np * 2 + 1], a[i][0], a[i][1], a[i][2], a[i][3], bh[2], bh[3]);
                    MMA_F16(acc[i][np * 2 + 1], a[i][0], a[i][1], a[i][2], a[i][3], bl[2], bl[3]);
                }
            }
        }
    };

    load_chunk(0, 0);
    load_chunk(1, 1);

#pragma unroll 1
    for (int c = 0; c < 8; c++) {
        if (c < 6) asm volatile("cp.async.wait_group 1;" ::: "memory");
        else       asm volatile("cp.async.wait_group 0;" ::: "memory");
        __syncthreads();
        compute(c & 1);
        __syncthreads();
        if (c + 2 < 8) load_chunk(c + 2, c & 1);
    }

    // ---------------- epilogue ----------------
    if (OUTMODE == 1) {
        uint32_t* C = (uint32_t*)Cout;   // fp16 pairs
#pragma unroll
        for (int i = 0; i < 2; i++) {
            int r0 = row0 + wm * 32 + i * 16 + gq;
#pragma unroll
            for (int n = 0; n < 8; n++) {
                int col = col0 + wn * 64 + n * 8 + tq * 2;
                float b0 = bias[col], b1 = bias[col + 1];
                float v0 = fmaxf(acc[i][n][0] + b0, 0.f);
                float v1 = fmaxf(acc[i][n][1] + b1, 0.f);
                float v2 = fmaxf(acc[i][n][2] + b0, 0.f);
                float v3 = fmaxf(acc[i][n][3] + b1, 0.f);
                if (r0 < M)
                    C[(size_t)r0 * (HID / 2) + (col >> 1)] = pack_h2(v0, v1);
                if (r0 + 8 < M)
                    C[(size_t)(r0 + 8) * (HID / 2) + (col >> 1)] = pack_h2(v2, v3);
            }
        }
    } else {
        float s[16], q[16];
#pragma unroll
        for (int k = 0; k < 16; k++) { s[k] = 0.f; q[k] = 0.f; }
#pragma unroll
        for (int i = 0; i < 2; i++) {
            int r0 = row0 + wm * 32 + i * 16 + gq;
            bool ok0 = (r0 < M), ok1 = (r0 + 8 < M);
#pragma unroll
            for (int n = 0; n < 8; n++) {
                int col = col0 + wn * 64 + n * 8 + tq * 2;
                float b0 = bias[col], b1 = bias[col + 1];
                float v0 = acc[i][n][0] + b0, v1 = acc[i][n][1] + b1;
                float v2 = acc[i][n][2] + b0, v3 = acc[i][n][3] + b1;
                float* C = (float*)Cout;
                if (ok0)
                    *reinterpret_cast<float2*>(C + (size_t)r0 * HID + col) = make_float2(v0, v1);
                if (ok1)
                    *reinterpret_cast<float2*>(C + (size_t)(r0 + 8) * HID + col) = make_float2(v2, v3);
                float a0 = ok0 ? v0 : 0.f, a1 = ok0 ? v1 : 0.f;
                float a2 = ok1 ? v2 : 0.f, a3 = ok1 ? v3 : 0.f;
                s[n * 2 + 0] += a0 + a2;
                s[n * 2 + 1] += a1 + a3;
                q[n * 2 + 0] += a0 * a0 + a2 * a2;
                q[n * 2 + 1] += a1 * a1 + a3 * a3;
            }
        }
#pragma unroll
        for (int k = 0; k < 16; k++) {
#pragma unroll
            for (int off = 4; off < 32; off <<= 1) {
                s[k] += __shfl_xor_sync(0xffffffffu, s[k], off);
                q[k] += __shfl_xor_sync(0xffffffffu, q[k], off);
            }
        }
        if (lane < 4) {
#pragma unroll
            for (int k = 0; k < 16; k++) {
                int col = col0 + wn * 64 + (k >> 1) * 8 + lane * 2 + (k & 1);
                atomicAdd(&colsum[col], s[k]);
                atomicAdd(&colsq[col], q[k]);
            }
        }
    }
}

// ---------------- W transpose + split (once per launch) ----------------
__global__ void wsplit_kernel(const float* __restrict__ W1s,
                              const float* __restrict__ W2s) {
    __shared__ float tile[32][33];
    const int m = blockIdx.z;
    const float* W = (m & 1) ? (W2s + (size_t)(m >> 1) * HID * HID)
                             : (W1s + (size_t)(m >> 1) * HID * HID);
    const int kb = blockIdx.y * 32, nb = blockIdx.x * 32;
    const int tx = threadIdx.x, ty = threadIdx.y;
#pragma unroll
    for (int i = 0; i < 32; i += 8)
        tile[ty + i][tx] = W[(size_t)(kb + ty + i) * HID + nb + tx];
    __syncthreads();
#pragma unroll
    for (int i = 0; i < 32; i += 8) {
        int n = nb + ty + i, k = kb + tx;
        float v = tile[tx][ty + i];
        __half h = __float2half(v);
        float res = v - __half2float(h);
        size_t o = (size_t)m * HID * HID + (size_t)n * HID + k;
        g_whi[o] = h;
        g_wlo[o] = __float2half(res);
    }
}

// ---------------- projection: h = x @ Wp + bp ----------------
__global__ void __launch_bounds__(256) proj_kernel(const float* __restrict__ x,
                                                   const float* __restrict__ Wp,
                                                   const float* __restrict__ bp) {
    __shared__ float xs[32][IN_DIM];
    __shared__ float ws[IN_DIM * HID];
    const int tid = threadIdx.x;
    for (int i = tid; i < IN_DIM * HID; i += 256) ws[i] = Wp[i];
    const int row0 = blockIdx.x * 32;
    for (int i = tid; i < 32 * IN_DIM; i += 256) {
        int r = i / IN_DIM, k = i % IN_DIM;
        xs[r][k] = (row0 + r < N_NODES) ? x[(row0 + r) * IN_DIM + k] : 0.f;
    }
    __syncthreads();
    float acc[32];
#pragma unroll
    for (int r = 0; r < 32; r++) acc[r] = 0.f;
    const int col = tid;
#pragma unroll
    for (int k = 0; k < IN_DIM; k++) {
        float w = ws[k * HID + col];
#pragma unroll
        for (int r = 0; r < 32; r++) acc[r] = fmaf(xs[r][k], w, acc[r]);
    }
    const float b = bp[col];
    for (int r = 0; r < 32; r++) {
        int rr = row0 + r;
        if (rr < N_NODES) g_h[rr * HID + col] = acc[r] + b;
    }
}

// ---------------- CSR build ----------------
__global__ void zero_deg_kernel() {
    int i = blockIdx.x * blockDim.x + threadIdx.x;
    if (i < N_NODES) g_deg[i] = 0;
}
__global__ void count_kernel(const int* __restrict__ dst) {
    int e = blockIdx.x * blockDim.x + threadIdx.x;
    if (e < N_EDGES) atomicAdd(&g_deg[dst[e]], 1);
}
__global__ void __launch_bounds__(1024) scan_kernel() {
    const int CH = (N_NODES + 1023) / 1024;
    const int tid = threadIdx.x;
    const int base = tid * CH;
    int s = 0;
    for (int i = 0; i < CH; i++) {
        int idx = base + i;
        if (idx < N_NODES) s += g_deg[idx];
    }
    __shared__ int bs[1024];
    bs[tid] = s;
    __syncthreads();
    for (int off = 1; off < 1024; off <<= 1) {
        int v = (tid >= off) ? bs[tid - off] : 0;
        __syncthreads();
        bs[tid] += v;
        __syncthreads();
    }
    int running = bs[tid] - s;
    for (int i = 0; i < CH; i++) {
        int idx = base + i;
        if (idx < N_NODES) {
            g_off[idx] = running;
            running += g_deg[idx];
            g_fill[idx] = 0;
        }
    }
    if (tid == 1023) g_off[N_NODES] = bs[1023];
}
__global__ void fill_kernel(const int* __restrict__ src, const int* __restrict__ dst) {
    int e = blockIdx.x * blockDim.x + threadIdx.x;
    if (e >= N_EDGES) return;
    int d = dst[e];
    int pos = g_off[d] + atomicAdd(&g_fill[d], 1);
    g_csr[pos] = src[e];
}

// ------- gather: zp[n] = fp16((1+eps)*f(in[n]) + sum f(in[j])); zero stats -------
template <bool BN>
__global__ void __launch_bounds__(256) gather_kernel(const float* __restrict__ eps, int l,
                                                     const float* __restrict__ gammas,
                                                     const float* __restrict__ betas) {
    const int tid = threadIdx.x;
    if (blockIdx.x == 0) {
        g_colsum2[l & 1][tid] = 0.f;
        g_colsq2[l & 1][tid] = 0.f;
    }
    const int node = blockIdx.x * 4 + (tid >> 6);
    const int lane = tid & 63;
    if (node >= N_NODES) return;
    const float s = 1.f + eps[l];
    const int lo = g_off[node];
    const int hi = g_off[node + 1];
    const float4* in4 = reinterpret_cast<const float4*>(BN ? g_z : g_h);
    float4 sc, sh;
    if (BN) {
        const int pp = (l - 1) & 1;
        const float inv = 1.f / (float)N_NODES;
        float scv[4], shv[4];
#pragma unroll
        for (int j = 0; j < 4; j++) {
            int c = lane * 4 + j;
            float mu = g_colsum2[pp][c] * inv;
            float var = g_colsq2[pp][c] * inv - mu * mu;
            float rs = rsqrtf(var + BN_EPS);
            scv[j] = gammas[(l - 1) * HID + c] * rs;
            shv[j] = betas[(l - 1) * HID + c] - mu * scv[j];
        }
        sc = make_float4(scv[0], scv[1], scv[2], scv[3]);
        sh = make_float4(shv[0], shv[1], shv[2], shv[3]);
    }
    auto f = [&](float4 v) {
        if (BN) {
            v.x = fmaxf(fmaf(v.x, sc.x, sh.x), 0.f);
            v.y = fmaxf(fmaf(v.y, sc.y, sh.y), 0.f);
            v.z = fmaxf(fmaf(v.z, sc.z, sh.z), 0.f);
            v.w = fmaxf(fmaf(v.w, sc.w, sh.w), 0.f);
        }
        return v;
    };
    float4 a = f(in4[node * 64 + lane]);
    a.x *= s; a.y *= s; a.z *= s; a.w *= s;
    for (int i = lo; i < hi; i++) {
        int sr = g_csr[i];
        float4 v = f(in4[sr * 64 + lane]);
        a.x += v.x; a.y += v.y; a.z += v.z; a.w += v.w;
    }
    uint2 p;
    p.x = pack_h2(a.x, a.y);
    p.y = pack_h2(a.z, a.w);
    reinterpret_cast<uint2*>(g_zp)[node * 64 + lane] = p;
}

// ---------------- pooling with fused final BN+relu (stats parity 0) ----------------
__global__ void pool_kernel(const int* __restrict__ batch,
                            const float* __restrict__ gammas,
                            const float* __restrict__ betas) {
    const int g = blockIdx.x;
    const int col = threadIdx.x;
    __shared__ int s_lo, s_hi;
    if (col < 2) {
        int target = g + col;
        int lo = 0, hi = N_NODES;
        while (lo < hi) {
            int mid = (lo + hi) >> 1;
            if (batch[mid] < target) lo = mid + 1; else hi = mid;
        }
        if (col == 0) s_lo = lo; else s_hi = lo;
    }
    __syncthreads();
    const int lo = s_lo, hi = s_hi;
    const float inv = 1.f / (float)N_NODES;
    const float mu = g_colsum2[0][col] * inv;
    const float var = g_colsq2[0][col] * inv - mu * mu;
    const float rs = rsqrtf(var + BN_EPS);
    const float sc = gammas[(LAYERS - 1) * HID + col] * rs;
    const float sh = betas[(LAYERS - 1) * HID + col] - mu * sc;
    float s = 0.f;
    for (int r = lo; r < hi; r++)
        s += fmaxf(fmaf(g_z[r * HID + col], sc, sh), 0.f);
    g_pool[g * HID + col] = s / fmaxf((float)(hi - lo), 1.f);
}

// ---------------- readout SGEMM (fp32 SIMT, small M) ----------------
template <bool RELU>
__global__ void __launch_bounds__(256) sgemm_kernel(const float* __restrict__ A,
                                                    const float* __restrict__ B,
                                                    const float* __restrict__ bias,
                                                    float* __restrict__ C,
                                                    int M, int N, int K) {
    __shared__ float As[8][128];
    __shared__ float Bs[8][128];
    const int tid = threadIdx.x;
    const int row0 = blockIdx.x * 128;
    const int col0 = blockIdx.y * 128;
    const int tr = (tid >> 4) << 3;
    const int tc = (tid & 15) << 3;
    const int arow = tid >> 1;
    const int ak4 = (tid & 1) * 4;
    const int brow = tid >> 5;
    const int bcol = (tid & 31) * 4;
    float acc[8][8];
#pragma unroll
    for (int i = 0; i < 8; i++)
#pragma unroll
        for (int j = 0; j < 8; j++) acc[i][j] = 0.f;
    const int gar = row0 + arow;
    const bool arow_ok = (gar < M);
    for (int k0 = 0; k0 < K; k0 += 8) {
        float4 av = make_float4(0.f, 0.f, 0.f, 0.f);
        if (arow_ok)
            av = *reinterpret_cast<const float4*>(A + (size_t)gar * K + k0 + ak4);
        As[ak4 + 0][arow] = av.x;
        As[ak4 + 1][arow] = av.y;
        As[ak4 + 2][arow] = av.z;
        As[ak4 + 3][arow] = av.w;
        float4 bv = *reinterpret_cast<const float4*>(B + (size_t)(k0 + brow) * N + col0 + bcol);
        *reinterpret_cast<float4*>(&Bs[brow][bcol]) = bv;
        __syncthreads();
#pragma unroll
        for (int k = 0; k < 8; k++) {
            float ra[8], rb[8];
#pragma unroll
            for (int i = 0; i < 8; i++) ra[i] = As[k][tr + i];
#pragma unroll
            for (int j = 0; j < 8; j++) rb[j] = Bs[k][tc + j];
#pragma unroll
            for (int i = 0; i < 8; i++)
#pragma unroll
                for (int j = 0; j < 8; j++) acc[i][j] = fmaf(ra[i], rb[j], acc[i][j]);
        }
        __syncthreads();
    }
#pragma unroll
    for (int i = 0; i < 8; i++) {
        int r = row0 + tr + i;
        if (r >= M) break;
#pragma unroll
        for (int j = 0; j < 8; j += 4) {
            float4 v;
            v.x = acc[i][j + 0] + bias[col0 + tc + j + 0];
            v.y = acc[i][j + 1] + bias[col0 + tc + j + 1];
            v.z = acc[i][j + 2] + bias[col0 + tc + j + 2];
            v.w = acc[i][j + 3] + bias[col0 + tc + j + 3];
            if (RELU) {
                v.x = fmaxf(v.x, 0.f); v.y = fmaxf(v.y, 0.f);
                v.z = fmaxf(v.z, 0.f); v.w = fmaxf(v.w, 0.f);
            }
            *reinterpret_cast<float4*>(C + (size_t)r * N + col0 + tc + j) = v;
        }
    }
}

__global__ void readout2_kernel(const float* __restrict__ Wr2,
                                const float* __restrict__ br2,
                                float* __restrict__ out) {
    __shared__ float red[256];
    const int g = blockIdx.x;
    const int t = threadIdx.x;
    red[t] = g_r1[g * HID + t] * Wr2[t];
    __syncthreads();
    for (int s = 128; s > 0; s >>= 1) {
        if (t < s) red[t] += red[t + s];
        __syncthreads();
    }
    if (t == 0) out[g] = red[0] + br2[0];
}

// ---------------- host launcher ----------------
extern "C" void kernel_launch(void* const* d_in, const int* in_sizes, int n_in,
                              void* d_out, int out_size) {
    const float* x      = (const float*)d_in[0];
    const int*   ei     = (const int*)d_in[1];
    const int*   batch  = (const int*)d_in[2];
    const float* Wp     = (const float*)d_in[3];
    const float* bp     = (const float*)d_in[4];
    const float* eps    = (const float*)d_in[5];
    const float* W1s    = (const float*)d_in[6];
    const float* b1s    = (const float*)d_in[7];
    const float* W2s    = (const float*)d_in[8];
    const float* b2s    = (const float*)d_in[9];
    const float* gammas = (const float*)d_in[10];
    const float* betas  = (const float*)d_in[11];
    const float* Wr1    = (const float*)d_in[12];
    const float* br1    = (const float*)d_in[13];
    const float* Wr2    = (const float*)d_in[14];
    const float* br2    = (const float*)d_in[15];
    float* out = (float*)d_out;

    const int* src = ei;
    const int* dst = ei + N_EDGES;

    void *p_z, *p_zp, *p_tp, *p_pool, *p_r1, *p_whi, *p_wlo, *p_cs, *p_cq;
    cudaGetSymbolAddress(&p_z, g_z);
    cudaGetSymbolAddress(&p_zp, g_zp);
    cudaGetSymbolAddress(&p_tp, g_tp);
    cudaGetSymbolAddress(&p_pool, g_pool);
    cudaGetSymbolAddress(&p_r1, g_r1);
    cudaGetSymbolAddress(&p_whi, g_whi);
    cudaGetSymbolAddress(&p_wlo, g_wlo);
    cudaGetSymbolAddress(&p_cs, g_colsum2);
    cudaGetSymbolAddress(&p_cq, g_colsq2);
    float* dz = (float*)p_z;
    __half* dzp = (__half*)p_zp;
    __half* dtp = (__half*)p_tp;
    float* dpool = (float*)p_pool;
    float* dr1 = (float*)p_r1;
    __half* dwhi = (__half*)p_whi;
    __half* dwlo = (__half*)p_wlo;
    float* dcs = (float*)p_cs;
    float* dcq = (float*)p_cq;

    cudaFuncSetAttribute(gemm_mma_kernel<0>,
                         cudaFuncAttributeMaxDynamicSharedMemorySize, GEMM_SMEM);
    cudaFuncSetAttribute(gemm_mma_kernel<1>,
                         cudaFuncAttributeMaxDynamicSharedMemorySize, GEMM_SMEM);

    // CSR build + W split + projection
    zero_deg_kernel<<<(N_NODES + 255) / 256, 256>>>();
    count_kernel<<<(N_EDGES + 255) / 256, 256>>>(dst);
    scan_kernel<<<1, 1024>>>();
    fill_kernel<<<(N_EDGES + 255) / 256, 256>>>(src, dst);
    wsplit_kernel<<<dim3(8, 8, 2 * LAYERS), dim3(32, 8)>>>(W1s, W2s);
    proj_kernel<<<(N_NODES + 31) / 32, 256>>>(x, Wp, bp);

    const dim3 ggrid((N_NODES + 127) / 128, 2);
    const size_t WSZ = (size_t)HID * HID;

    for (int l = 0; l < LAYERS; l++) {
        if (l == 0)
            gather_kernel<false><<<(N_NODES + 3) / 4, 256>>>(eps, l, gammas, betas);
        else
            gather_kernel<true><<<(N_NODES + 3) / 4, 256>>>(eps, l, gammas, betas);
        gemm_mma_kernel<1><<<ggrid, 256, GEMM_SMEM>>>(
            dzp, dwhi + (2 * l) * WSZ, dwlo + (2 * l) * WSZ, b1s + l * HID,
            dtp, nullptr, nullptr, N_NODES);
        gemm_mma_kernel<0><<<ggrid, 256, GEMM_SMEM>>>(
            dtp, dwhi + (2 * l + 1) * WSZ, dwlo + (2 * l + 1) * WSZ, b2s + l * HID,
            dz, dcs + (l & 1) * HID, dcq + (l & 1) * HID, N_NODES);
    }

    pool_kernel<<<N_GRAPHS, 256>>>(batch, gammas, betas);

    const dim3 rgrid(N_GRAPHS / 128, HID / 128);
    sgemm_kernel<true><<<rgrid, 256>>>(dpool, Wr1, br1, dr1, N_GRAPHS, HID, HID);
    readout2_kernel<<<N_GRAPHS, 256>>>(Wr2, br2, out);
}

// round 10
// speedup vs baseline: 1.4500x; 1.0288x over previous
#include <cuda_runtime.h>
#include <cuda_fp16.h>
#include <cuda_bf16.h>
#include <cstdint>

#define N_NODES 100000
#define N_EDGES 300000
#define N_GRAPHS 2048
#define IN_DIM 38
#define HID 256
#define LAYERS 5
#define BN_EPS 1e-5f

// ---------------- device scratch ----------------
__device__ __half g_h[N_NODES * HID];         // fp16 features (proj out)
__device__ __half g_z[N_NODES * HID];         // fp16 GEMM2 output (pre-BN)
__device__ __half g_zp[N_NODES * HID];        // fp16 GEMM1 input
__device__ __half g_tp[N_NODES * HID];        // fp16 GEMM1 out / GEMM2 in
__device__ __half g_whi[2 * LAYERS * HID * HID];  // W^T hi, [mat][n][k]
__device__ __half g_wlo[2 * LAYERS * HID * HID];  // W^T lo (fp16 residual)
__device__ float g_colsum2[2][HID];
__device__ float g_colsq2[2][HID];
__device__ float g_pool[N_GRAPHS * HID];
__device__ float g_r1[N_GRAPHS * HID];
__device__ int g_deg[N_NODES];
__device__ int g_fill[N_NODES];
__device__ int g_off[N_NODES + 1];
__device__ int g_csr[N_EDGES];

__device__ __forceinline__ uint32_t smem_u32(const void* p) {
    uint32_t a;
    asm("{ .reg .u64 t; cvta.to.shared.u64 t, %1; cvt.u32.u64 %0, t; }"
        : "=r"(a) : "l"(p));
    return a;
}

__device__ __forceinline__ uint32_t pack_h2(float x, float y) {
    __half2 h = __floats2half2_rn(x, y);
    return *reinterpret_cast<uint32_t*>(&h);
}

__device__ __forceinline__ float4 unpack_h4(uint2 u) {
    __half2 h0 = *reinterpret_cast<__half2*>(&u.x);
    __half2 h1 = *reinterpret_cast<__half2*>(&u.y);
    float2 f0 = __half22float2(h0);
    float2 f1 = __half22float2(h1);
    return make_float4(f0.x, f0.y, f1.x, f1.y);
}

#define MMA_F16(c, a0, a1, a2, a3, b0, b1)                                     \
    asm volatile(                                                              \
        "mma.sync.aligned.m16n8k16.row.col.f32.f16.f16.f32 "                   \
        "{%0,%1,%2,%3}, {%4,%5,%6,%7}, {%8,%9}, {%0,%1,%2,%3};"                \
        : "+f"((c)[0]), "+f"((c)[1]), "+f"((c)[2]), "+f"((c)[3])               \
        : "r"(a0), "r"(a1), "r"(a2), "r"(a3), "r"(b0), "r"(b1))

#define LDMX4(r, addr)                                                         \
    asm volatile("ldmatrix.sync.aligned.m8n8.x4.shared.b16 {%0,%1,%2,%3}, [%4];" \
        : "=r"((r)[0]), "=r"((r)[1]), "=r"((r)[2]), "=r"((r)[3]) : "r"(addr))

#define CP_ASYNC16(dst, src) \
    asm volatile("cp.async.ca.shared.global [%0], [%1], 16;" \
                 :: "r"(dst), "l"(src) : "memory")
#define CP_ASYNC16_Z(dst, src, n) \
    asm volatile("cp.async.ca.shared.global [%0], [%1], 16, %2;" \
                 :: "r"(dst), "l"(src), "r"(n) : "memory")
#define CP_COMMIT() asm volatile("cp.async.commit_group;" ::: "memory")

// stage: A fp16 128 rows x 80B (64B data + 16B pad) = 10240B; BH/BL 128 x 80B
#define STG 30720
#define A_ST(s)  ((s) * STG)
#define BH_ST(s) ((s) * STG + 10240)
#define BL_ST(s) ((s) * STG + 20480)
#define GEMM_SMEM (2 * STG)

// ====== GEMM: C[M,256] = A_f16 @ (Whi+Wlo)[n][k]^T + bias (2-term fp16 split) ======
// OUTMODE 0: fp16 out (no relu) + fused fp32 stats; OUTMODE 1: relu + fp16 out.
template <int OUTMODE>
__global__ void __launch_bounds__(256, 2)
gemm_mma_kernel(const __half* __restrict__ Ap,
                const __half* __restrict__ Whi,
                const __half* __restrict__ Wlo,
                const float* __restrict__ bias,
                void* __restrict__ Cout,
                float* __restrict__ colsum, float* __restrict__ colsq, int M) {
    extern __shared__ char sm[];
    const uint32_t smb = smem_u32(sm);
    const int tid = threadIdx.x;
    const int lane = tid & 31;
    const int wid = tid >> 5;
    const int wm = wid & 3;
    const int wn = wid >> 2;
    const int gq = lane >> 2;
    const int tq = lane & 3;
    const int row0 = blockIdx.x * 128;
    const int col0 = blockIdx.y * 128;

    float acc[2][8][4];
#pragma unroll
    for (int i = 0; i < 2; i++)
#pragma unroll
        for (int n = 0; n < 8; n++)
#pragma unroll
            for (int q = 0; q < 4; q++) acc[i][n][q] = 0.f;

    auto load_chunk = [&](int c, int s) {
        const int k0 = c * 32;
        // A: 128 rows x 64B fp16
#pragma unroll
        for (int i = 0; i < 2; i++) {
            int idx = tid + 256 * i;
            int r = idx >> 2, q = idx & 3;
            int gr = row0 + r;
            int nb = (gr < M) ? 16 : 0;
            int grc = (gr < M) ? gr : (M - 1);
            const char* src = (const char*)(Ap + (size_t)grc * HID + k0 + q * 8);
            CP_ASYNC16_Z(smb + A_ST(s) + r * 80 + q * 16, src, nb);
        }
        // B hi/lo: 128 n-rows x 64B each
#pragma unroll
        for (int i = 0; i < 4; i++) {
            int idx = tid + 256 * i;
            int half_ = idx >> 9, i2 = idx & 511;
            int r = i2 >> 2, q = i2 & 3;
            const __half* W = half_ ? Wlo : Whi;
            const char* src = (const char*)(W + (size_t)(col0 + r) * HID + k0 + q * 8);
            uint32_t dst = smb + (half_ ? BL_ST(s) : BH_ST(s)) + r * 80 + q * 16;
            CP_ASYNC16(dst, src);
        }
        CP_COMMIT();
    };

    // ldmatrix lane mappings
    const int a_lrow = lane & 15;
    const int a_koff = (lane >> 4) * 16;
    const int b_lrow = ((lane & 16) >> 1) + (lane & 7);
    const int b_koff = ((lane >> 3) & 1) * 16;

    auto compute = [&](int s) {
#pragma unroll
        for (int j = 0; j < 2; j++) {
            uint32_t a[2][4];
#pragma unroll
            for (int i = 0; i < 2; i++) {
                uint32_t ro = (uint32_t)(wm * 32 + i * 16 + a_lrow) * 80 + j * 32 + a_koff;
                LDMX4(a[i], smb + A_ST(s) + ro);
            }
#pragma unroll
            for (int np = 0; np < 4; np++) {
                uint32_t bh[4], bl[4];
                uint32_t bo = (uint32_t)(wn * 64 + np * 16 + b_lrow) * 80 + j * 32 + b_koff;
                LDMX4(bh, smb + BH_ST(s) + bo);
                LDMX4(bl, smb + BL_ST(s) + bo);
#pragma unroll
                for (int i = 0; i < 2; i++) {
                    MMA_F16(acc[i][np * 2],     a[i][0], a[i][1], a[i][2], a[i][3], bh[0], bh[1]);
                    MMA_F16(acc[i][np * 2],     a[i][0], a[i][1], a[i][2], a[i][3], bl[0], bl[1]);
                    MMA_F16(acc[i][np * 2 + 1], a[i][0], a[i][1], a[i][2], a[i][3], bh[2], bh[3]);
                    MMA_F16(acc[i][np * 2 + 1], a[i][0], a[i][1], a[i][2], a[i][3], bl[2], bl[3]);
                }
            }
        }
    };

    load_chunk(0, 0);
    load_chunk(1, 1);

#pragma unroll 1
    for (int c = 0; c < 8; c++) {
        if (c < 6) asm volatile("cp.async.wait_group 1;" ::: "memory");
        else       asm volatile("cp.async.wait_group 0;" ::: "memory");
        __syncthreads();
        compute(c & 1);
        __syncthreads();
        if (c + 2 < 8) load_chunk(c + 2, c & 1);
    }

    // ---------------- epilogue ----------------
    uint32_t* C = (uint32_t*)Cout;   // fp16 pairs
    if (OUTMODE == 1) {
#pragma unroll
        for (int i = 0; i < 2; i++) {
            int r0 = row0 + wm * 32 + i * 16 + gq;
#pragma unroll
            for (int n = 0; n < 8; n++) {
                int col = col0 + wn * 64 + n * 8 + tq * 2;
                float b0 = bias[col], b1 = bias[col + 1];
                float v0 = fmaxf(acc[i][n][0] + b0, 0.f);
                float v1 = fmaxf(acc[i][n][1] + b1, 0.f);
                float v2 = fmaxf(acc[i][n][2] + b0, 0.f);
                float v3 = fmaxf(acc[i][n][3] + b1, 0.f);
                if (r0 < M)
                    C[(size_t)r0 * (HID / 2) + (col >> 1)] = pack_h2(v0, v1);
                if (r0 + 8 < M)
                    C[(size_t)(r0 + 8) * (HID / 2) + (col >> 1)] = pack_h2(v2, v3);
            }
        }
    } else {
        float s[16], q[16];
#pragma unroll
        for (int k = 0; k < 16; k++) { s[k] = 0.f; q[k] = 0.f; }
#pragma unroll
        for (int i = 0; i < 2; i++) {
            int r0 = row0 + wm * 32 + i * 16 + gq;
            bool ok0 = (r0 < M), ok1 = (r0 + 8 < M);
#pragma unroll
            for (int n = 0; n < 8; n++) {
                int col = col0 + wn * 64 + n * 8 + tq * 2;
                float b0 = bias[col], b1 = bias[col + 1];
                float v0 = acc[i][n][0] + b0, v1 = acc[i][n][1] + b1;
                float v2 = acc[i][n][2] + b0, v3 = acc[i][n][3] + b1;
                if (ok0)
                    C[(size_t)r0 * (HID / 2) + (col >> 1)] = pack_h2(v0, v1);
                if (ok1)
                    C[(size_t)(r0 + 8) * (HID / 2) + (col >> 1)] = pack_h2(v2, v3);
                float a0 = ok0 ? v0 : 0.f, a1 = ok0 ? v1 : 0.f;
                float a2 = ok1 ? v2 : 0.f, a3 = ok1 ? v3 : 0.f;
                s[n * 2 + 0] += a0 + a2;
                s[n * 2 + 1] += a1 + a3;
                q[n * 2 + 0] += a0 * a0 + a2 * a2;
                q[n * 2 + 1] += a1 * a1 + a3 * a3;
            }
        }
#pragma unroll
        for (int k = 0; k < 16; k++) {
#pragma unroll
            for (int off = 4; off < 32; off <<= 1) {
                s[k] += __shfl_xor_sync(0xffffffffu, s[k], off);
                q[k] += __shfl_xor_sync(0xffffffffu, q[k], off);
            }
        }
        if (lane < 4) {
#pragma unroll
            for (int k = 0; k < 16; k++) {
                int col = col0 + wn * 64 + (k >> 1) * 8 + lane * 2 + (k & 1);
                atomicAdd(&colsum[col], s[k]);
                atomicAdd(&colsq[col], q[k]);
            }
        }
    }
}

// ---------------- W transpose + split (once per launch) ----------------
__global__ void wsplit_kernel(const float* __restrict__ W1s,
                              const float* __restrict__ W2s) {
    __shared__ float tile[32][33];
    const int m = blockIdx.z;
    const float* W = (m & 1) ? (W2s + (size_t)(m >> 1) * HID * HID)
                             : (W1s + (size_t)(m >> 1) * HID * HID);
    const int kb = blockIdx.y * 32, nb = blockIdx.x * 32;
    const int tx = threadIdx.x, ty = threadIdx.y;
#pragma unroll
    for (int i = 0; i < 32; i += 8)
        tile[ty + i][tx] = W[(size_t)(kb + ty + i) * HID + nb + tx];
    __syncthreads();
#pragma unroll
    for (int i = 0; i < 32; i += 8) {
        int n = nb + ty + i, k = kb + tx;
        float v = tile[tx][ty + i];
        __half h = __float2half(v);
        float res = v - __half2float(h);
        size_t o = (size_t)m * HID * HID + (size_t)n * HID + k;
        g_whi[o] = h;
        g_wlo[o] = __float2half(res);
    }
}

// ---------------- projection: h = fp16(x @ Wp + bp) ----------------
__global__ void __launch_bounds__(256) proj_kernel(const float* __restrict__ x,
                                                   const float* __restrict__ Wp,
                                                   const float* __restrict__ bp) {
    __shared__ float xs[32][IN_DIM];
    __shared__ float ws[IN_DIM * HID];
    const int tid = threadIdx.x;
    for (int i = tid; i < IN_DIM * HID; i += 256) ws[i] = Wp[i];
    const int row0 = blockIdx.x * 32;
    for (int i = tid; i < 32 * IN_DIM; i += 256) {
        int r = i / IN_DIM, k = i % IN_DIM;
        xs[r][k] = (row0 + r < N_NODES) ? x[(row0 + r) * IN_DIM + k] : 0.f;
    }
    __syncthreads();
    float acc[32];
#pragma unroll
    for (int r = 0; r < 32; r++) acc[r] = 0.f;
    const int col = tid;
#pragma unroll
    for (int k = 0; k < IN_DIM; k++) {
        float w = ws[k * HID + col];
#pragma unroll
        for (int r = 0; r < 32; r++) acc[r] = fmaf(xs[r][k], w, acc[r]);
    }
    const float b = bp[col];
    for (int r = 0; r < 32; r++) {
        int rr = row0 + r;
        if (rr < N_NODES) g_h[rr * HID + col] = __float2half(acc[r] + b);
    }
}

// ---------------- CSR build ----------------
__global__ void zero_deg_kernel() {
    int i = blockIdx.x * blockDim.x + threadIdx.x;
    if (i < N_NODES) g_deg[i] = 0;
}
__global__ void count_kernel(const int* __restrict__ dst) {
    int e = blockIdx.x * blockDim.x + threadIdx.x;
    if (e < N_EDGES) atomicAdd(&g_deg[dst[e]], 1);
}
__global__ void __launch_bounds__(1024) scan_kernel() {
    const int CH = (N_NODES + 1023) / 1024;
    const int tid = threadIdx.x;
    const int base = tid * CH;
    int s = 0;
    for (int i = 0; i < CH; i++) {
        int idx = base + i;
        if (idx < N_NODES) s += g_deg[idx];
    }
    __shared__ int bs[1024];
    bs[tid] = s;
    __syncthreads();
    for (int off = 1; off < 1024; off <<= 1) {
        int v = (tid >= off) ? bs[tid - off] : 0;
        __syncthreads();
        bs[tid] += v;
        __syncthreads();
    }
    int running = bs[tid] - s;
    for (int i = 0; i < CH; i++) {
        int idx = base + i;
        if (idx < N_NODES) {
            g_off[idx] = running;
            running += g_deg[idx];
            g_fill[idx] = 0;
        }
    }
    if (tid == 1023) g_off[N_NODES] = bs[1023];
}
__global__ void fill_kernel(const int* __restrict__ src, const int* __restrict__ dst) {
    int e = blockIdx.x * blockDim.x + threadIdx.x;
    if (e >= N_EDGES) return;
    int d = dst[e];
    int pos = g_off[d] + atomicAdd(&g_fill[d], 1);
    g_csr[pos] = src[e];
}

// ------- gather: zp[n] = fp16((1+eps)*f(in[n]) + sum f(in[j])); zero stats -------
template <bool BN>
__global__ void __launch_bounds__(256) gather_kernel(const float* __restrict__ eps, int l,
                                                     const float* __restrict__ gammas,
                                                     const float* __restrict__ betas) {
    const int tid = threadIdx.x;
    if (blockIdx.x == 0) {
        g_colsum2[l & 1][tid] = 0.f;
        g_colsq2[l & 1][tid] = 0.f;
    }
    const int node = blockIdx.x * 4 + (tid >> 6);
    const int lane = tid & 63;
    if (node >= N_NODES) return;
    const float s = 1.f + eps[l];
    const int lo = g_off[node];
    const int hi = g_off[node + 1];
    const uint2* in2 = reinterpret_cast<const uint2*>(BN ? g_z : g_h);
    float4 sc, sh;
    if (BN) {
        const int pp = (l - 1) & 1;
        const float inv = 1.f / (float)N_NODES;
        float scv[4], shv[4];
#pragma unroll
        for (int j = 0; j < 4; j++) {
            int c = lane * 4 + j;
            float mu = g_colsum2[pp][c] * inv;
            float var = g_colsq2[pp][c] * inv - mu * mu;
            float rs = rsqrtf(var + BN_EPS);
            scv[j] = gammas[(l - 1) * HID + c] * rs;
            shv[j] = betas[(l - 1) * HID + c] - mu * scv[j];
        }
        sc = make_float4(scv[0], scv[1], scv[2], scv[3]);
        sh = make_float4(shv[0], shv[1], shv[2], shv[3]);
    }
    auto f = [&](float4 v) {
        if (BN) {
            v.x = fmaxf(fmaf(v.x, sc.x, sh.x), 0.f);
            v.y = fmaxf(fmaf(v.y, sc.y, sh.y), 0.f);
            v.z = fmaxf(fmaf(v.z, sc.z, sh.z), 0.f);
            v.w = fmaxf(fmaf(v.w, sc.w, sh.w), 0.f);
        }
        return v;
    };
    float4 a = f(unpack_h4(in2[node * 64 + lane]));
    a.x *= s; a.y *= s; a.z *= s; a.w *= s;
    for (int i = lo; i < hi; i++) {
        int sr = g_csr[i];
        float4 v = f(unpack_h4(in2[sr * 64 + lane]));
        a.x += v.x; a.y += v.y; a.z += v.z; a.w += v.w;
    }
    uint2 p;
    p.x = pack_h2(a.x, a.y);
    p.y = pack_h2(a.z, a.w);
    reinterpret_cast<uint2*>(g_zp)[node * 64 + lane] = p;
}

// ---------------- pooling with fused final BN+relu (stats parity 0) ----------------
__global__ void pool_kernel(const int* __restrict__ batch,
                            const float* __restrict__ gammas,
                            const float* __restrict__ betas) {
    const int g = blockIdx.x;
    const int col = threadIdx.x;
    __shared__ int s_lo, s_hi;
    if (col < 2) {
        int target = g + col;
        int lo = 0, hi = N_NODES;
        while (lo < hi) {
            int mid = (lo + hi) >> 1;
            if (batch[mid] < target) lo = mid + 1; else hi = mid;
        }
        if (col == 0) s_lo = lo; else s_hi = lo;
    }
    __syncthreads();
    const int lo = s_lo, hi = s_hi;
    const float inv = 1.f / (float)N_NODES;
    const float mu = g_colsum2[0][col] * inv;
    const float var = g_colsq2[0][col] * inv - mu * mu;
    const float rs = rsqrtf(var + BN_EPS);
    const float sc = gammas[(LAYERS - 1) * HID + col] * rs;
    const float sh = betas[(LAYERS - 1) * HID + col] - mu * sc;
    float s = 0.f;
    for (int r = lo; r < hi; r++)
        s += fmaxf(fmaf(__half2float(g_z[r * HID + col]), sc, sh), 0.f);
    g_pool[g * HID + col] = s / fmaxf((float)(hi - lo), 1.f);
}

// ---------------- readout SGEMM (fp32 SIMT, small M) ----------------
template <bool RELU>
__global__ void __launch_bounds__(256) sgemm_kernel(const float* __restrict__ A,
                                                    const float* __restrict__ B,
                                                    const float* __restrict__ bias,
                                                    float* __restrict__ C,
                                                    int M, int N, int K) {
    __shared__ float As[8][128];
    __shared__ float Bs[8][128];
    const int tid = threadIdx.x;
    const int row0 = blockIdx.x * 128;
    const int col0 = blockIdx.y * 128;
    const int tr = (tid >> 4) << 3;
    const int tc = (tid & 15) << 3;
    const int arow = tid >> 1;
    const int ak4 = (tid & 1) * 4;
    const int brow = tid >> 5;
    const int bcol = (tid & 31) * 4;
    float acc[8][8];
#pragma unroll
    for (int i = 0; i < 8; i++)
#pragma unroll
        for (int j = 0; j < 8; j++) acc[i][j] = 0.f;
    const int gar = row0 + arow;
    const bool arow_ok = (gar < M);
    for (int k0 = 0; k0 < K; k0 += 8) {
        float4 av = make_float4(0.f, 0.f, 0.f, 0.f);
        if (arow_ok)
            av = *reinterpret_cast<const float4*>(A + (size_t)gar * K + k0 + ak4);
        As[ak4 + 0][arow] = av.x;
        As[ak4 + 1][arow] = av.y;
        As[ak4 + 2][arow] = av.z;
        As[ak4 + 3][arow] = av.w;
        float4 bv = *reinterpret_cast<const float4*>(B + (size_t)(k0 + brow) * N + col0 + bcol);
        *reinterpret_cast<float4*>(&Bs[brow][bcol]) = bv;
        __syncthreads();
#pragma unroll
        for (int k = 0; k < 8; k++) {
            float ra[8], rb[8];
#pragma unroll
            for (int i = 0; i < 8; i++) ra[i] = As[k][tr + i];
#pragma unroll
            for (int j = 0; j < 8; j++) rb[j] = Bs[k][tc + j];
#pragma unroll
            for (int i = 0; i < 8; i++)
#pragma unroll
                for (int j = 0; j < 8; j++) acc[i][j] = fmaf(ra[i], rb[j], acc[i][j]);
        }
        __syncthreads();
    }
#pragma unroll
    for (int i = 0; i < 8; i++) {
        int r = row0 + tr + i;
        if (r >= M) break;
#pragma unroll
        for (int j = 0; j < 8; j += 4) {
            float4 v;
            v.x = acc[i][j + 0] + bias[col0 + tc + j + 0];
            v.y = acc[i][j + 1] + bias[col0 + tc + j + 1];
            v.z = acc[i][j + 2] + bias[col0 + tc + j + 2];
            v.w = acc[i][j + 3] + bias[col0 + tc + j + 3];
            if (RELU) {
                v.x = fmaxf(v.x, 0.f); v.y = fmaxf(v.y, 0.f);
                v.z = fmaxf(v.z, 0.f); v.w = fmaxf(v.w, 0.f);
            }
            *reinterpret_cast<float4*>(C + (size_t)r * N + col0 + tc + j) = v;
        }
    }
}

__global__ void readout2_kernel(const float* __restrict__ Wr2,
                                const float* __restrict__ br2,
                                float* __restrict__ out) {
    __shared__ float red[256];
    const int g = blockIdx.x;
    const int t = threadIdx.x;
    red[t] = g_r1[g * HID + t] * Wr2[t];
    __syncthreads();
    for (int s = 128; s > 0; s >>= 1) {
        if (t < s) red[t] += red[t + s];
        __syncthreads();
    }
    if (t == 0) out[g] = red[0] + br2[0];
}

// ---------------- host launcher ----------------
extern "C" void kernel_launch(void* const* d_in, const int* in_sizes, int n_in,
                              void* d_out, int out_size) {
    const float* x      = (const float*)d_in[0];
    const int*   ei     = (const int*)d_in[1];
    const int*   batch  = (const int*)d_in[2];
    const float* Wp     = (const float*)d_in[3];
    const float* bp     = (const float*)d_in[4];
    const float* eps    = (const float*)d_in[5];
    const float* W1s    = (const float*)d_in[6];
    const float* b1s    = (const float*)d_in[7];
    const float* W2s    = (const float*)d_in[8];
    const float* b2s    = (const float*)d_in[9];
    const float* gammas = (const float*)d_in[10];
    const float* betas  = (const float*)d_in[11];
    const float* Wr1    = (const float*)d_in[12];
    const float* br1    = (const float*)d_in[13];
    const float* Wr2    = (const float*)d_in[14];
    const float* br2    = (const float*)d_in[15];
    float* out = (float*)d_out;

    const int* src = ei;
    const int* dst = ei + N_EDGES;

    void *p_z, *p_zp, *p_tp, *p_pool, *p_r1, *p_whi, *p_wlo, *p_cs, *p_cq;
    cudaGetSymbolAddress(&p_z, g_z);
    cudaGetSymbolAddress(&p_zp, g_zp);
    cudaGetSymbolAddress(&p_tp, g_tp);
    cudaGetSymbolAddress(&p_pool, g_pool);
    cudaGetSymbolAddress(&p_r1, g_r1);
    cudaGetSymbolAddress(&p_whi, g_whi);
    cudaGetSymbolAddress(&p_wlo, g_wlo);
    cudaGetSymbolAddress(&p_cs, g_colsum2);
    cudaGetSymbolAddress(&p_cq, g_colsq2);
    __half* dz = (__half*)p_z;
    __half* dzp = (__half*)p_zp;
    __half* dtp = (__half*)p_tp;
    float* dpool = (float*)p_pool;
    float* dr1 = (float*)p_r1;
    __half* dwhi = (__half*)p_whi;
    __half* dwlo = (__half*)p_wlo;
    float* dcs = (float*)p_cs;
    float* dcq = (float*)p_cq;

    cudaFuncSetAttribute(gemm_mma_kernel<0>,
                         cudaFuncAttributeMaxDynamicSharedMemorySize, GEMM_SMEM);
    cudaFuncSetAttribute(gemm_mma_kernel<1>,
                         cudaFuncAttributeMaxDynamicSharedMemorySize, GEMM_SMEM);

    // CSR build + W split + projection
    zero_deg_kernel<<<(N_NODES + 255) / 256, 256>>>();
    count_kernel<<<(N_EDGES + 255) / 256, 256>>>(dst);
    scan_kernel<<<1, 1024>>>();
    fill_kernel<<<(N_EDGES + 255) / 256, 256>>>(src, dst);
    wsplit_kernel<<<dim3(8, 8, 2 * LAYERS), dim3(32, 8)>>>(W1s, W2s);
    proj_kernel<<<(N_NODES + 31) / 32, 256>>>(x, Wp, bp);

    const dim3 ggrid((N_NODES + 127) / 128, 2);
    const size_t WSZ = (size_t)HID * HID;

    for (int l = 0; l < LAYERS; l++) {
        if (l == 0)
            gather_kernel<false><<<(N_NODES + 3) / 4, 256>>>(eps, l, gammas, betas);
        else
            gather_kernel<true><<<(N_NODES + 3) / 4, 256>>>(eps, l, gammas, betas);
        gemm_mma_kernel<1><<<ggrid, 256, GEMM_SMEM>>>(
            dzp, dwhi + (2 * l) * WSZ, dwlo + (2 * l) * WSZ, b1s + l * HID,
            dtp, nullptr, nullptr, N_NODES);
        gemm_mma_kernel<0><<<ggrid, 256, GEMM_SMEM>>>(
            dtp, dwhi + (2 * l + 1) * WSZ, dwlo + (2 * l + 1) * WSZ, b2s + l * HID,
            dz, dcs + (l & 1) * HID, dcq + (l & 1) * HID, N_NODES);
    }

    pool_kernel<<<N_GRAPHS, 256>>>(batch, gammas, betas);

    const dim3 rgrid(N_GRAPHS / 128, HID / 128);
    sgemm_kernel<true><<<rgrid, 256>>>(dpool, Wr1, br1, dr1, N_GRAPHS, HID, HID);
    readout2_kernel<<<N_GRAPHS, 256>>>(Wr2, br2, out);
}

// round 11
// speedup vs baseline: 1.5843x; 1.0926x over previous
#include <cuda_runtime.h>
#include <cuda_fp16.h>
#include <cuda_bf16.h>
#include <cstdint>

#define N_NODES 100000
#define N_EDGES 300000
#define N_GRAPHS 2048
#define IN_DIM 38
#define HID 256
#define LAYERS 5
#define BN_EPS 1e-5f

// ---------------- device scratch ----------------
__device__ __half g_h[N_NODES * HID];         // fp16 features (proj out)
__device__ __half g_z[N_NODES * HID];         // fp16 GEMM2 output (pre-BN)
__device__ __half g_zp[N_NODES * HID];        // fp16 GEMM1 input
__device__ __half g_tp[N_NODES * HID];        // fp16 GEMM1 out / GEMM2 in
__device__ __half g_whi[2 * LAYERS * HID * HID];  // W^T hi, [mat][n][k]
__device__ __half g_wlo[2 * LAYERS * HID * HID];  // W^T lo (fp16 residual)
__device__ float g_colsum2[2][HID];
__device__ float g_colsq2[2][HID];
__device__ float g_pool[N_GRAPHS * HID];
__device__ float g_r1[N_GRAPHS * HID];
__device__ int g_deg[N_NODES];                // zero-init; re-zeroed by layer-0 gather
__device__ int g_fill[N_NODES];
__device__ int g_off[N_NODES + 1];
__device__ int g_csr[N_EDGES];

__device__ __forceinline__ uint32_t smem_u32(const void* p) {
    uint32_t a;
    asm("{ .reg .u64 t; cvta.to.shared.u64 t, %1; cvt.u32.u64 %0, t; }"
        : "=r"(a) : "l"(p));
    return a;
}

__device__ __forceinline__ uint32_t pack_h2(float x, float y) {
    __half2 h = __floats2half2_rn(x, y);
    return *reinterpret_cast<uint32_t*>(&h);
}

__device__ __forceinline__ float4 unpack_h4(uint2 u) {
    __half2 h0 = *reinterpret_cast<__half2*>(&u.x);
    __half2 h1 = *reinterpret_cast<__half2*>(&u.y);
    float2 f0 = __half22float2(h0);
    float2 f1 = __half22float2(h1);
    return make_float4(f0.x, f0.y, f1.x, f1.y);
}

#define MMA_F16(c, a0, a1, a2, a3, b0, b1)                                     \
    asm volatile(                                                              \
        "mma.sync.aligned.m16n8k16.row.col.f32.f16.f16.f32 "                   \
        "{%0,%1,%2,%3}, {%4,%5,%6,%7}, {%8,%9}, {%0,%1,%2,%3};"                \
        : "+f"((c)[0]), "+f"((c)[1]), "+f"((c)[2]), "+f"((c)[3])               \
        : "r"(a0), "r"(a1), "r"(a2), "r"(a3), "r"(b0), "r"(b1))

#define LDMX4(r, addr)                                                         \
    asm volatile("ldmatrix.sync.aligned.m8n8.x4.shared.b16 {%0,%1,%2,%3}, [%4];" \
        : "=r"((r)[0]), "=r"((r)[1]), "=r"((r)[2]), "=r"((r)[3]) : "r"(addr))

#define CP_ASYNC16(dst, src) \
    asm volatile("cp.async.ca.shared.global [%0], [%1], 16;" \
                 :: "r"(dst), "l"(src) : "memory")
#define CP_ASYNC16_Z(dst, src, n) \
    asm volatile("cp.async.ca.shared.global [%0], [%1], 16, %2;" \
                 :: "r"(dst), "l"(src), "r"(n) : "memory")
#define CP_COMMIT() asm volatile("cp.async.commit_group;" ::: "memory")

// stage: A fp16 128 rows x 80B = 10240B; BH/BL 128 x 80B; 3 stages
#define STG 30720
#define A_ST(s)  ((s) * STG)
#define BH_ST(s) ((s) * STG + 10240)
#define BL_ST(s) ((s) * STG + 20480)
#define GEMM_SMEM (3 * STG)

// ====== GEMM: C[M,256] = A_f16 @ W[n][k]^T + bias ======
// TERMS=2: W = Whi + Wlo (2 MMAs/product); TERMS=1: W = Whi only.
// OUTMODE 0: fp16 out (no relu) + fused fp32 stats; OUTMODE 1: relu + fp16 out.
template <int OUTMODE, int TERMS>
__global__ void __launch_bounds__(256, 2)
gemm_mma_kernel(const __half* __restrict__ Ap,
                const __half* __restrict__ Whi,
                const __half* __restrict__ Wlo,
                const float* __restrict__ bias,
                void* __restrict__ Cout,
                float* __restrict__ colsum, float* __restrict__ colsq, int M) {
    extern __shared__ char sm[];
    const uint32_t smb = smem_u32(sm);
    const int tid = threadIdx.x;
    const int lane = tid & 31;
    const int wid = tid >> 5;
    const int wm = wid & 3;
    const int wn = wid >> 2;
    const int gq = lane >> 2;
    const int tq = lane & 3;
    const int row0 = blockIdx.x * 128;
    const int col0 = blockIdx.y * 128;

    float acc[2][8][4];
#pragma unroll
    for (int i = 0; i < 2; i++)
#pragma unroll
        for (int n = 0; n < 8; n++)
#pragma unroll
            for (int q = 0; q < 4; q++) acc[i][n][q] = 0.f;

    auto load_chunk = [&](int c, int s) {
        const int k0 = c * 32;
        // A: 128 rows x 64B fp16
#pragma unroll
        for (int i = 0; i < 2; i++) {
            int idx = tid + 256 * i;
            int r = idx >> 2, q = idx & 3;
            int gr = row0 + r;
            int nb = (gr < M) ? 16 : 0;
            int grc = (gr < M) ? gr : (M - 1);
            const char* src = (const char*)(Ap + (size_t)grc * HID + k0 + q * 8);
            CP_ASYNC16_Z(smb + A_ST(s) + r * 80 + q * 16, src, nb);
        }
        // B: hi (and lo if TERMS==2): 128 n-rows x 64B each
#pragma unroll
        for (int i = 0; i < 2 * TERMS; i++) {
            int idx = tid + 256 * i;
            int half_ = idx >> 9, i2 = idx & 511;
            int r = i2 >> 2, q = i2 & 3;
            const __half* W = half_ ? Wlo : Whi;
            const char* src = (const char*)(W + (size_t)(col0 + r) * HID + k0 + q * 8);
            uint32_t dst = smb + (half_ ? BL_ST(s) : BH_ST(s)) + r * 80 + q * 16;
            CP_ASYNC16(dst, src);
        }
        CP_COMMIT();
    };

    // ldmatrix lane mappings
    const int a_lrow = lane & 15;
    const int a_koff = (lane >> 4) * 16;
    const int b_lrow = ((lane & 16) >> 1) + (lane & 7);
    const int b_koff = ((lane >> 3) & 1) * 16;

    auto compute = [&](int s) {
#pragma unroll
        for (int j = 0; j < 2; j++) {
            uint32_t a[2][4];
#pragma unroll
            for (int i = 0; i < 2; i++) {
                uint32_t ro = (uint32_t)(wm * 32 + i * 16 + a_lrow) * 80 + j * 32 + a_koff;
                LDMX4(a[i], smb + A_ST(s) + ro);
            }
#pragma unroll
            for (int np = 0; np < 4; np++) {
                uint32_t bh[4], bl[4];
                uint32_t bo = (uint32_t)(wn * 64 + np * 16 + b_lrow) * 80 + j * 32 + b_koff;
                LDMX4(bh, smb + BH_ST(s) + bo);
                if (TERMS == 2) LDMX4(bl, smb + BL_ST(s) + bo);
#pragma unroll
                for (int i = 0; i < 2; i++) {
                    MMA_F16(acc[i][np * 2],     a[i][0], a[i][1], a[i][2], a[i][3], bh[0], bh[1]);
                    MMA_F16(acc[i][np * 2 + 1], a[i][0], a[i][1], a[i][2], a[i][3], bh[2], bh[3]);
                    if (TERMS == 2) {
                        MMA_F16(acc[i][np * 2],     a[i][0], a[i][1], a[i][2], a[i][3], bl[0], bl[1]);
                        MMA_F16(acc[i][np * 2 + 1], a[i][0], a[i][1], a[i][2], a[i][3], bl[2], bl[3]);
                    }
                }
            }
        }
    };

    // 3-stage pipeline, ONE sync per chunk.
    // Invariant at top of iter c: pending cp.async groups = {c, c+1}.
    load_chunk(0, 0);
    load_chunk(1, 1);

#pragma unroll 1
    for (int c = 0; c < 8; c++) {
        if (c < 7) asm volatile("cp.async.wait_group 1;" ::: "memory");
        else       asm volatile("cp.async.wait_group 0;" ::: "memory");
        __syncthreads();            // chunk c visible to all; compute(c-1) finished by all
        compute(c % 3);
        if (c + 2 < 8) load_chunk(c + 2, (c + 2) % 3);  // stage released by compute(c-1)
    }

    // ---------------- epilogue ----------------
    uint32_t* C = (uint32_t*)Cout;   // fp16 pairs
    if (OUTMODE == 1) {
#pragma unroll
        for (int i = 0; i < 2; i++) {
            int r0 = row0 + wm * 32 + i * 16 + gq;
#pragma unroll
            for (int n = 0; n < 8; n++) {
                int col = col0 + wn * 64 + n * 8 + tq * 2;
                float b0 = bias[col], b1 = bias[col + 1];
                float v0 = fmaxf(acc[i][n][0] + b0, 0.f);
                float v1 = fmaxf(acc[i][n][1] + b1, 0.f);
                float v2 = fmaxf(acc[i][n][2] + b0, 0.f);
                float v3 = fmaxf(acc[i][n][3] + b1, 0.f);
                if (r0 < M)
                    C[(size_t)r0 * (HID / 2) + (col >> 1)] = pack_h2(v0, v1);
                if (r0 + 8 < M)
                    C[(size_t)(r0 + 8) * (HID / 2) + (col >> 1)] = pack_h2(v2, v3);
            }
        }
    } else {
        float s[16], q[16];
#pragma unroll
        for (int k = 0; k < 16; k++) { s[k] = 0.f; q[k] = 0.f; }
#pragma unroll
        for (int i = 0; i < 2; i++) {
            int r0 = row0 + wm * 32 + i * 16 + gq;
            bool ok0 = (r0 < M), ok1 = (r0 + 8 < M);
#pragma unroll
            for (int n = 0; n < 8; n++) {
                int col = col0 + wn * 64 + n * 8 + tq * 2;
                float b0 = bias[col], b1 = bias[col + 1];
                float v0 = acc[i][n][0] + b0, v1 = acc[i][n][1] + b1;
                float v2 = acc[i][n][2] + b0, v3 = acc[i][n][3] + b1;
                if (ok0)
                    C[(size_t)r0 * (HID / 2) + (col >> 1)] = pack_h2(v0, v1);
                if (ok1)
                    C[(size_t)(r0 + 8) * (HID / 2) + (col >> 1)] = pack_h2(v2, v3);
                float a0 = ok0 ? v0 : 0.f, a1 = ok0 ? v1 : 0.f;
                float a2 = ok1 ? v2 : 0.f, a3 = ok1 ? v3 : 0.f;
                s[n * 2 + 0] += a0 + a2;
                s[n * 2 + 1] += a1 + a3;
                q[n * 2 + 0] += a0 * a0 + a2 * a2;
                q[n * 2 + 1] += a1 * a1 + a3 * a3;
            }
        }
#pragma unroll
        for (int k = 0; k < 16; k++) {
#pragma unroll
            for (int off = 4; off < 32; off <<= 1) {
                s[k] += __shfl_xor_sync(0xffffffffu, s[k], off);
                q[k] += __shfl_xor_sync(0xffffffffu, q[k], off);
            }
        }
        if (lane < 4) {
#pragma unroll
            for (int k = 0; k < 16; k++) {
                int col = col0 + wn * 64 + (k >> 1) * 8 + lane * 2 + (k & 1);
                atomicAdd(&colsum[col], s[k]);
                atomicAdd(&colsq[col], q[k]);
            }
        }
    }
}

// ------- fused W transpose/split (blocks [0,640)) + projection -------
#define WSPLIT_BLOCKS (8 * 8 * 2 * LAYERS)
#define PROJ_BLOCKS ((N_NODES + 31) / 32)
__global__ void __launch_bounds__(256) wsplit_proj_kernel(
        const float* __restrict__ W1s, const float* __restrict__ W2s,
        const float* __restrict__ x, const float* __restrict__ Wp,
        const float* __restrict__ bp) {
    __shared__ char sbuf[44032];
    const int tid = threadIdx.x;
    if (blockIdx.x < WSPLIT_BLOCKS) {
        float (*tile)[33] = reinterpret_cast<float(*)[33]>(sbuf);
        const int m = blockIdx.x / 64;
        const int rem = blockIdx.x & 63;
        const int kb = (rem >> 3) * 32, nb = (rem & 7) * 32;
        const int tx = tid & 31, ty = tid >> 5;
        const float* W = (m & 1) ? (W2s + (size_t)(m >> 1) * HID * HID)
                                 : (W1s + (size_t)(m >> 1) * HID * HID);
#pragma unroll
        for (int i = 0; i < 32; i += 8)
            tile[ty + i][tx] = W[(size_t)(kb + ty + i) * HID + nb + tx];
        __syncthreads();
#pragma unroll
        for (int i = 0; i < 32; i += 8) {
            int n = nb + ty + i, k = kb + tx;
            float v = tile[tx][ty + i];
            __half h = __float2half(v);
            float res = v - __half2float(h);
            size_t o = (size_t)m * HID * HID + (size_t)n * HID + k;
            g_whi[o] = h;
            g_wlo[o] = __float2half(res);
        }
        return;
    }
    // projection: h = fp16(x @ Wp + bp)
    float (*xs)[IN_DIM] = reinterpret_cast<float(*)[IN_DIM]>(sbuf);
    float* ws = reinterpret_cast<float*>(sbuf + 32 * IN_DIM * 4);
    for (int i = tid; i < IN_DIM * HID; i += 256) ws[i] = Wp[i];
    const int row0 = (blockIdx.x - WSPLIT_BLOCKS) * 32;
    for (int i = tid; i < 32 * IN_DIM; i += 256) {
        int r = i / IN_DIM, k = i % IN_DIM;
        xs[r][k] = (row0 + r < N_NODES) ? x[(row0 + r) * IN_DIM + k] : 0.f;
    }
    __syncthreads();
    float acc[32];
#pragma unroll
    for (int r = 0; r < 32; r++) acc[r] = 0.f;
    const int col = tid;
#pragma unroll
    for (int k = 0; k < IN_DIM; k++) {
        float w = ws[k * HID + col];
#pragma unroll
        for (int r = 0; r < 32; r++) acc[r] = fmaf(xs[r][k], w, acc[r]);
    }
    const float b = bp[col];
    for (int r = 0; r < 32; r++) {
        int rr = row0 + r;
        if (rr < N_NODES) g_h[rr * HID + col] = __float2half(acc[r] + b);
    }
}

// ---------------- CSR build ----------------
// g_deg is zero at first call (static init) and re-zeroed by layer-0 gather
// AFTER scan consumed it, keeping every graph replay identical.
__global__ void count_kernel(const int* __restrict__ dst) {
    int e = blockIdx.x * blockDim.x + threadIdx.x;
    if (e < N_EDGES) atomicAdd(&g_deg[dst[e]], 1);
}
__global__ void __launch_bounds__(1024) scan_kernel() {
    const int CH = (N_NODES + 1023) / 1024;
    const int tid = threadIdx.x;
    const int base = tid * CH;
    int s = 0;
    for (int i = 0; i < CH; i++) {
        int idx = base + i;
        if (idx < N_NODES) s += g_deg[idx];
    }
    __shared__ int bs[1024];
    bs[tid] = s;
    __syncthreads();
    for (int off = 1; off < 1024; off <<= 1) {
        int v = (tid >= off) ? bs[tid - off] : 0;
        __syncthreads();
        bs[tid] += v;
        __syncthreads();
    }
    int running = bs[tid] - s;
    for (int i = 0; i < CH; i++) {
        int idx = base + i;
        if (idx < N_NODES) {
            g_off[idx] = running;
            running += g_deg[idx];
            g_fill[idx] = 0;
        }
    }
    if (tid == 1023) g_off[N_NODES] = bs[1023];
}
__global__ void fill_kernel(const int* __restrict__ src, const int* __restrict__ dst) {
    int e = blockIdx.x * blockDim.x + threadIdx.x;
    if (e >= N_EDGES) return;
    int d = dst[e];
    int pos = g_off[d] + atomicAdd(&g_fill[d], 1);
    g_csr[pos] = src[e];
}

// ------- gather: zp[n] = fp16((1+eps)*f(in[n]) + sum f(in[j])); zero stats/deg -------
template <bool BN>
__global__ void __launch_bounds__(256) gather_kernel(const float* __restrict__ eps, int l,
                                                     const float* __restrict__ gammas,
                                                     const float* __restrict__ betas) {
    const int tid = threadIdx.x;
    if (blockIdx.x == 0) {
        g_colsum2[l & 1][tid] = 0.f;
        g_colsq2[l & 1][tid] = 0.f;
    }
    if (!BN) {  // layer 0: reset degree counters for the next graph replay
        int zi = blockIdx.x * 256 + tid;
        if (blockIdx.x < (N_NODES + 255) / 256 && zi < N_NODES) g_deg[zi] = 0;
    }
    const int node = blockIdx.x * 4 + (tid >> 6);
    const int lane = tid & 63;
    if (node >= N_NODES) return;
    const float s = 1.f + eps[l];
    const int lo = g_off[node];
    const int hi = g_off[node + 1];
    const uint2* in2 = reinterpret_cast<const uint2*>(BN ? g_z : g_h);
    float4 sc, sh;
    if (BN) {
        const int pp = (l - 1) & 1;
        const float inv = 1.f / (float)N_NODES;
        float scv[4], shv[4];
#pragma unroll
        for (int j = 0; j < 4; j++) {
            int c = lane * 4 + j;
            float mu = g_colsum2[pp][c] * inv;
            float var = g_colsq2[pp][c] * inv - mu * mu;
            float rs = rsqrtf(var + BN_EPS);
            scv[j] = gammas[(l - 1) * HID + c] * rs;
            shv[j] = betas[(l - 1) * HID + c] - mu * scv[j];
        }
        sc = make_float4(scv[0], scv[1], scv[2], scv[3]);
        sh = make_float4(shv[0], shv[1], shv[2], shv[3]);
    }
    auto f = [&](float4 v) {
        if (BN) {
            v.x = fmaxf(fmaf(v.x, sc.x, sh.x), 0.f);
            v.y = fmaxf(fmaf(v.y, sc.y, sh.y), 0.f);
            v.z = fmaxf(fmaf(v.z, sc.z, sh.z), 0.f);
            v.w = fmaxf(fmaf(v.w, sc.w, sh.w), 0.f);
        }
        return v;
    };
    float4 a = f(unpack_h4(in2[node * 64 + lane]));
    a.x *= s; a.y *= s; a.z *= s; a.w *= s;
    for (int i = lo; i < hi; i++) {
        int sr = g_csr[i];
        float4 v = f(unpack_h4(in2[sr * 64 + lane]));
        a.x += v.x; a.y += v.y; a.z += v.z; a.w += v.w;
    }
    uint2 p;
    p.x = pack_h2(a.x, a.y);
    p.y = pack_h2(a.z, a.w);
    reinterpret_cast<uint2*>(g_zp)[node * 64 + lane] = p;
}

// ---------------- pooling with fused final BN+relu (stats parity 0) ----------------
__global__ void pool_kernel(const int* __restrict__ batch,
                            const float* __restrict__ gammas,
                            const float* __restrict__ betas) {
    const int g = blockIdx.x;
    const int col = threadIdx.x;
    __shared__ int s_lo, s_hi;
    if (col < 2) {
        int target = g + col;
        int lo = 0, hi = N_NODES;
        while (lo < hi) {
            int mid = (lo + hi) >> 1;
            if (batch[mid] < target) lo = mid + 1; else hi = mid;
        }
        if (col == 0) s_lo = lo; else s_hi = lo;
    }
    __syncthreads();
    const int lo = s_lo, hi = s_hi;
    const float inv = 1.f / (float)N_NODES;
    const float mu = g_colsum2[0][col] * inv;
    const float var = g_colsq2[0][col] * inv - mu * mu;
    const float rs = rsqrtf(var + BN_EPS);
    const float sc = gammas[(LAYERS - 1) * HID + col] * rs;
    const float sh = betas[(LAYERS - 1) * HID + col] - mu * sc;
    float s = 0.f;
    for (int r = lo; r < hi; r++)
        s += fmaxf(fmaf(__half2float(g_z[r * HID + col]), sc, sh), 0.f);
    g_pool[g * HID + col] = s / fmaxf((float)(hi - lo), 1.f);
}

// ---------------- readout SGEMM (fp32 SIMT, small M) ----------------
template <bool RELU>
__global__ void __launch_bounds__(256) sgemm_kernel(const float* __restrict__ A,
                                                    const float* __restrict__ B,
                                                    const float* __restrict__ bias,
                                                    float* __restrict__ C,
                                                    int M, int N, int K) {
    __shared__ float As[8][128];
    __shared__ float Bs[8][128];
    const int tid = threadIdx.x;
    const int row0 = blockIdx.x * 128;
    const int col0 = blockIdx.y * 128;
    const int tr = (tid >> 4) << 3;
    const int tc = (tid & 15) << 3;
    const int arow = tid >> 1;
    const int ak4 = (tid & 1) * 4;
    const int brow = tid >> 5;
    const int bcol = (tid & 31) * 4;
    float acc[8][8];
#pragma unroll
    for (int i = 0; i < 8; i++)
#pragma unroll
        for (int j = 0; j < 8; j++) acc[i][j] = 0.f;
    const int gar = row0 + arow;
    const bool arow_ok = (gar < M);
    for (int k0 = 0; k0 < K; k0 += 8) {
        float4 av = make_float4(0.f, 0.f, 0.f, 0.f);
        if (arow_ok)
            av = *reinterpret_cast<const float4*>(A + (size_t)gar * K + k0 + ak4);
        As[ak4 + 0][arow] = av.x;
        As[ak4 + 1][arow] = av.y;
        As[ak4 + 2][arow] = av.z;
        As[ak4 + 3][arow] = av.w;
        float4 bv = *reinterpret_cast<const float4*>(B + (size_t)(k0 + brow) * N + col0 + bcol);
        *reinterpret_cast<float4*>(&Bs[brow][bcol]) = bv;
        __syncthreads();
#pragma unroll
        for (int k = 0; k < 8; k++) {
            float ra[8], rb[8];
#pragma unroll
            for (int i = 0; i < 8; i++) ra[i] = As[k][tr + i];
#pragma unroll
            for (int j = 0; j < 8; j++) rb[j] = Bs[k][tc + j];
#pragma unroll
            for (int i = 0; i < 8; i++)
#pragma unroll
                for (int j = 0; j < 8; j++) acc[i][j] = fmaf(ra[i], rb[j], acc[i][j]);
        }
        __syncthreads();
    }
#pragma unroll
    for (int i = 0; i < 8; i++) {
        int r = row0 + tr + i;
        if (r >= M) break;
#pragma unroll
        for (int j = 0; j < 8; j += 4) {
            float4 v;
            v.x = acc[i][j + 0] + bias[col0 + tc + j + 0];
            v.y = acc[i][j + 1] + bias[col0 + tc + j + 1];
            v.z = acc[i][j + 2] + bias[col0 + tc + j + 2];
            v.w = acc[i][j + 3] + bias[col0 + tc + j + 3];
            if (RELU) {
                v.x = fmaxf(v.x, 0.f); v.y = fmaxf(v.y, 0.f);
                v.z = fmaxf(v.z, 0.f); v.w = fmaxf(v.w, 0.f);
            }
            *reinterpret_cast<float4*>(C + (size_t)r * N + col0 + tc + j) = v;
        }
    }
}

__global__ void readout2_kernel(const float* __restrict__ Wr2,
                                const float* __restrict__ br2,
                                float* __restrict__ out) {
    __shared__ float red[256];
    const int g = blockIdx.x;
    const int t = threadIdx.x;
    red[t] = g_r1[g * HID + t] * Wr2[t];
    __syncthreads();
    for (int s = 128; s > 0; s >>= 1) {
        if (t < s) red[t] += red[t + s];
        __syncthreads();
    }
    if (t == 0) out[g] = red[0] + br2[0];
}

// ---------------- host launcher ----------------
extern "C" void kernel_launch(void* const* d_in, const int* in_sizes, int n_in,
                              void* d_out, int out_size) {
    const float* x      = (const float*)d_in[0];
    const int*   ei     = (const int*)d_in[1];
    const int*   batch  = (const int*)d_in[2];
    const float* Wp     = (const float*)d_in[3];
    const float* bp     = (const float*)d_in[4];
    const float* eps    = (const float*)d_in[5];
    const float* W1s    = (const float*)d_in[6];
    const float* b1s    = (const float*)d_in[7];
    const float* W2s    = (const float*)d_in[8];
    const float* b2s    = (const float*)d_in[9];
    const float* gammas = (const float*)d_in[10];
    const float* betas  = (const float*)d_in[11];
    const float* Wr1    = (const float*)d_in[12];
    const float* br1    = (const float*)d_in[13];
    const float* Wr2    = (const float*)d_in[14];
    const float* br2    = (const float*)d_in[15];
    float* out = (float*)d_out;

    const int* src = ei;
    const int* dst = ei + N_EDGES;

    void *p_z, *p_zp, *p_tp, *p_pool, *p_r1, *p_whi, *p_wlo, *p_cs, *p_cq;
    cudaGetSymbolAddress(&p_z, g_z);
    cudaGetSymbolAddress(&p_zp, g_zp);
    cudaGetSymbolAddress(&p_tp, g_tp);
    cudaGetSymbolAddress(&p_pool, g_pool);
    cudaGetSymbolAddress(&p_r1, g_r1);
    cudaGetSymbolAddress(&p_whi, g_whi);
    cudaGetSymbolAddress(&p_wlo, g_wlo);
    cudaGetSymbolAddress(&p_cs, g_colsum2);
    cudaGetSymbolAddress(&p_cq, g_colsq2);
    __half* dz = (__half*)p_z;
    __half* dzp = (__half*)p_zp;
    __half* dtp = (__half*)p_tp;
    float* dpool = (float*)p_pool;
    float* dr1 = (float*)p_r1;
    __half* dwhi = (__half*)p_whi;
    __half* dwlo = (__half*)p_wlo;
    float* dcs = (float*)p_cs;
    float* dcq = (float*)p_cq;

    cudaFuncSetAttribute(gemm_mma_kernel<0, 2>,
                         cudaFuncAttributeMaxDynamicSharedMemorySize, GEMM_SMEM);
    cudaFuncSetAttribute(gemm_mma_kernel<1, 1>,
                         cudaFuncAttributeMaxDynamicSharedMemorySize, GEMM_SMEM);

    // CSR build + W split + projection (g_deg re-zeroed by layer-0 gather)
    count_kernel<<<(N_EDGES + 255) / 256, 256>>>(dst);
    scan_kernel<<<1, 1024>>>();
    fill_kernel<<<(N_EDGES + 255) / 256, 256>>>(src, dst);
    wsplit_proj_kernel<<<WSPLIT_BLOCKS + PROJ_BLOCKS, 256>>>(W1s, W2s, x, Wp, bp);

    const dim3 ggrid((N_NODES + 127) / 128, 2);
    const size_t WSZ = (size_t)HID * HID;

    for (int l = 0; l < LAYERS; l++) {
        if (l == 0)
            gather_kernel<false><<<(N_NODES + 3) / 4, 256>>>(eps, l, gammas, betas);
        else
            gather_kernel<true><<<(N_NODES + 3) / 4, 256>>>(eps, l, gammas, betas);
        gemm_mma_kernel<1, 1><<<ggrid, 256, GEMM_SMEM>>>(
            dzp, dwhi + (2 * l) * WSZ, dwlo + (2 * l) * WSZ, b1s + l * HID,
            dtp, nullptr, nullptr, N_NODES);
        gemm_mma_kernel<0, 2><<<ggrid, 256, GEMM_SMEM>>>(
            dtp, dwhi + (2 * l + 1) * WSZ, dwlo + (2 * l + 1) * WSZ, b2s + l * HID,
            dz, dcs + (l & 1) * HID, dcq + (l & 1) * HID, N_NODES);
    }

    pool_kernel<<<N_GRAPHS, 256>>>(batch, gammas, betas);

    const dim3 rgrid(N_GRAPHS / 128, HID / 128);
    sgemm_kernel<true><<<rgrid, 256>>>(dpool, Wr1, br1, dr1, N_GRAPHS, HID, HID);
    readout2_kernel<<<N_GRAPHS, 256>>>(Wr2, br2, out);
}

// round 12
// speedup vs baseline: 1.6615x; 1.0487x over previous
#include <cuda_runtime.h>
#include <cuda_fp16.h>
#include <cuda_bf16.h>
#include <cstdint>

#define N_NODES 100000
#define N_EDGES 300000
#define N_GRAPHS 2048
#define IN_DIM 38
#define HID 256
#define LAYERS 5
#define BN_EPS 1e-5f

// ---------------- device scratch ----------------
__device__ __half g_h[N_NODES * HID];         // fp16 features (proj out)
__device__ __half g_z[N_NODES * HID];         // fp16 GEMM2 output (pre-BN)
__device__ __half g_zp[N_NODES * HID];        // fp16 GEMM1 input
__device__ __half g_tp[N_NODES * HID];        // fp16 GEMM1 out / GEMM2 in
__device__ __half g_whi[2 * LAYERS * HID * HID];  // W^T fp16, [mat][n][k]
__device__ float g_colsum2[2][HID];
__device__ float g_colsq2[2][HID];
__device__ float g_pool[N_GRAPHS * HID];
__device__ float g_r1[N_GRAPHS * HID];
__device__ int g_deg[N_NODES];                // zero-init; re-zeroed by layer-0 gather
__device__ int g_fill[N_NODES];
__device__ int g_off[N_NODES + 1];
__device__ int g_csr[N_EDGES];

__device__ __forceinline__ uint32_t smem_u32(const void* p) {
    uint32_t a;
    asm("{ .reg .u64 t; cvta.to.shared.u64 t, %1; cvt.u32.u64 %0, t; }"
        : "=r"(a) : "l"(p));
    return a;
}

__device__ __forceinline__ uint32_t pack_h2(float x, float y) {
    __half2 h = __floats2half2_rn(x, y);
    return *reinterpret_cast<uint32_t*>(&h);
}

__device__ __forceinline__ float4 unpack_h4(uint2 u) {
    __half2 h0 = *reinterpret_cast<__half2*>(&u.x);
    __half2 h1 = *reinterpret_cast<__half2*>(&u.y);
    float2 f0 = __half22float2(h0);
    float2 f1 = __half22float2(h1);
    return make_float4(f0.x, f0.y, f1.x, f1.y);
}

#define MMA_F16(c, a0, a1, a2, a3, b0, b1)                                     \
    asm volatile(                                                              \
        "mma.sync.aligned.m16n8k16.row.col.f32.f16.f16.f32 "                   \
        "{%0,%1,%2,%3}, {%4,%5,%6,%7}, {%8,%9}, {%0,%1,%2,%3};"                \
        : "+f"((c)[0]), "+f"((c)[1]), "+f"((c)[2]), "+f"((c)[3])               \
        : "r"(a0), "r"(a1), "r"(a2), "r"(a3), "r"(b0), "r"(b1))

#define LDMX4(r, addr)                                                         \
    asm volatile("ldmatrix.sync.aligned.m8n8.x4.shared.b16 {%0,%1,%2,%3}, [%4];" \
        : "=r"((r)[0]), "=r"((r)[1]), "=r"((r)[2]), "=r"((r)[3]) : "r"(addr))

#define CP_ASYNC16(dst, src) \
    asm volatile("cp.async.ca.shared.global [%0], [%1], 16;" \
                 :: "r"(dst), "l"(src) : "memory")
#define CP_ASYNC16_Z(dst, src, n) \
    asm volatile("cp.async.ca.shared.global [%0], [%1], 16, %2;" \
                 :: "r"(dst), "l"(src), "r"(n) : "memory")
#define CP_COMMIT() asm volatile("cp.async.commit_group;" ::: "memory")

// stage: A fp16 128 rows x 80B = 10240B; B 128 x 80B; 3 stages
#define STG 20480
#define A_ST(s)  ((s) * STG)
#define BH_ST(s) ((s) * STG + 10240)
#define GEMM_SMEM (3 * STG)

// ====== GEMM: C[M,256] = A_f16 @ W_f16[n][k]^T + bias ======
// OUTMODE 0: fp16 out (no relu) + fused fp32 stats; OUTMODE 1: relu + fp16 out.
template <int OUTMODE>
__global__ void __launch_bounds__(256, 2)
gemm_mma_kernel(const __half* __restrict__ Ap,
                const __half* __restrict__ Whi,
                const float* __restrict__ bias,
                void* __restrict__ Cout,
                float* __restrict__ colsum, float* __restrict__ colsq, int M) {
    extern __shared__ char sm[];
    const uint32_t smb = smem_u32(sm);
    const int tid = threadIdx.x;
    const int lane = tid & 31;
    const int wid = tid >> 5;
    const int wm = wid & 3;
    const int wn = wid >> 2;
    const int gq = lane >> 2;
    const int tq = lane & 3;
    const int row0 = blockIdx.x * 128;
    const int col0 = blockIdx.y * 128;

    float acc[2][8][4];
#pragma unroll
    for (int i = 0; i < 2; i++)
#pragma unroll
        for (int n = 0; n < 8; n++)
#pragma unroll
            for (int q = 0; q < 4; q++) acc[i][n][q] = 0.f;

    auto load_chunk = [&](int c, int s) {
        const int k0 = c * 32;
        // A: 128 rows x 64B fp16
#pragma unroll
        for (int i = 0; i < 2; i++) {
            int idx = tid + 256 * i;
            int r = idx >> 2, q = idx & 3;
            int gr = row0 + r;
            int nb = (gr < M) ? 16 : 0;
            int grc = (gr < M) ? gr : (M - 1);
            const char* src = (const char*)(Ap + (size_t)grc * HID + k0 + q * 8);
            CP_ASYNC16_Z(smb + A_ST(s) + r * 80 + q * 16, src, nb);
        }
        // B: 128 n-rows x 64B
#pragma unroll
        for (int i = 0; i < 2; i++) {
            int idx = tid + 256 * i;
            int r = idx >> 2, q = idx & 3;
            const char* src = (const char*)(Whi + (size_t)(col0 + r) * HID + k0 + q * 8);
            CP_ASYNC16(smb + BH_ST(s) + r * 80 + q * 16, src);
        }
        CP_COMMIT();
    };

    // ldmatrix lane mappings
    const int a_lrow = lane & 15;
    const int a_koff = (lane >> 4) * 16;
    const int b_lrow = ((lane & 16) >> 1) + (lane & 7);
    const int b_koff = ((lane >> 3) & 1) * 16;

    auto compute = [&](int s) {
#pragma unroll
        for (int j = 0; j < 2; j++) {
            uint32_t a[2][4];
#pragma unroll
            for (int i = 0; i < 2; i++) {
                uint32_t ro = (uint32_t)(wm * 32 + i * 16 + a_lrow) * 80 + j * 32 + a_koff;
                LDMX4(a[i], smb + A_ST(s) + ro);
            }
#pragma unroll
            for (int np = 0; np < 4; np++) {
                uint32_t bh[4];
                uint32_t bo = (uint32_t)(wn * 64 + np * 16 + b_lrow) * 80 + j * 32 + b_koff;
                LDMX4(bh, smb + BH_ST(s) + bo);
#pragma unroll
                for (int i = 0; i < 2; i++) {
                    MMA_F16(acc[i][np * 2],     a[i][0], a[i][1], a[i][2], a[i][3], bh[0], bh[1]);
                    MMA_F16(acc[i][np * 2 + 1], a[i][0], a[i][1], a[i][2], a[i][3], bh[2], bh[3]);
                }
            }
        }
    };

    // 3-stage pipeline, one sync per chunk.
    load_chunk(0, 0);
    load_chunk(1, 1);

#pragma unroll 1
    for (int c = 0; c < 8; c++) {
        if (c < 7) asm volatile("cp.async.wait_group 1;" ::: "memory");
        else       asm volatile("cp.async.wait_group 0;" ::: "memory");
        __syncthreads();
        compute(c % 3);
        if (c + 2 < 8) load_chunk(c + 2, (c + 2) % 3);
    }

    // ---------------- epilogue ----------------
    uint32_t* C = (uint32_t*)Cout;   // fp16 pairs
    if (OUTMODE == 1) {
#pragma unroll
        for (int i = 0; i < 2; i++) {
            int r0 = row0 + wm * 32 + i * 16 + gq;
#pragma unroll
            for (int n = 0; n < 8; n++) {
                int col = col0 + wn * 64 + n * 8 + tq * 2;
                float b0 = bias[col], b1 = bias[col + 1];
                float v0 = fmaxf(acc[i][n][0] + b0, 0.f);
                float v1 = fmaxf(acc[i][n][1] + b1, 0.f);
                float v2 = fmaxf(acc[i][n][2] + b0, 0.f);
                float v3 = fmaxf(acc[i][n][3] + b1, 0.f);
                if (r0 < M)
                    C[(size_t)r0 * (HID / 2) + (col >> 1)] = pack_h2(v0, v1);
                if (r0 + 8 < M)
                    C[(size_t)(r0 + 8) * (HID / 2) + (col >> 1)] = pack_h2(v2, v3);
            }
        }
    } else {
        float s[16], q[16];
#pragma unroll
        for (int k = 0; k < 16; k++) { s[k] = 0.f; q[k] = 0.f; }
#pragma unroll
        for (int i = 0; i < 2; i++) {
            int r0 = row0 + wm * 32 + i * 16 + gq;
            bool ok0 = (r0 < M), ok1 = (r0 + 8 < M);
#pragma unroll
            for (int n = 0; n < 8; n++) {
                int col = col0 + wn * 64 + n * 8 + tq * 2;
                float b0 = bias[col], b1 = bias[col + 1];
                float v0 = acc[i][n][0] + b0, v1 = acc[i][n][1] + b1;
                float v2 = acc[i][n][2] + b0, v3 = acc[i][n][3] + b1;
                if (ok0)
                    C[(size_t)r0 * (HID / 2) + (col >> 1)] = pack_h2(v0, v1);
                if (ok1)
                    C[(size_t)(r0 + 8) * (HID / 2) + (col >> 1)] = pack_h2(v2, v3);
                float a0 = ok0 ? v0 : 0.f, a1 = ok0 ? v1 : 0.f;
                float a2 = ok1 ? v2 : 0.f, a3 = ok1 ? v3 : 0.f;
                s[n * 2 + 0] += a0 + a2;
                s[n * 2 + 1] += a1 + a3;
                q[n * 2 + 0] += a0 * a0 + a2 * a2;
                q[n * 2 + 1] += a1 * a1 + a3 * a3;
            }
        }
#pragma unroll
        for (int k = 0; k < 16; k++) {
#pragma unroll
            for (int off = 4; off < 32; off <<= 1) {
                s[k] += __shfl_xor_sync(0xffffffffu, s[k], off);
                q[k] += __shfl_xor_sync(0xffffffffu, q[k], off);
            }
        }
        if (lane < 4) {
#pragma unroll
            for (int k = 0; k < 16; k++) {
                int col = col0 + wn * 64 + (k >> 1) * 8 + lane * 2 + (k & 1);
                atomicAdd(&colsum[col], s[k]);
                atomicAdd(&colsq[col], q[k]);
            }
        }
    }
}

// ---------------- W transpose to fp16 (once per launch) ----------------
__global__ void wsplit_kernel(const float* __restrict__ W1s,
                              const float* __restrict__ W2s) {
    __shared__ float tile[32][33];
    const int m = blockIdx.z;
    const float* W = (m & 1) ? (W2s + (size_t)(m >> 1) * HID * HID)
                             : (W1s + (size_t)(m >> 1) * HID * HID);
    const int kb = blockIdx.y * 32, nb = blockIdx.x * 32;
    const int tx = threadIdx.x, ty = threadIdx.y;
#pragma unroll
    for (int i = 0; i < 32; i += 8)
        tile[ty + i][tx] = W[(size_t)(kb + ty + i) * HID + nb + tx];
    __syncthreads();
#pragma unroll
    for (int i = 0; i < 32; i += 8) {
        int n = nb + ty + i, k = kb + tx;
        g_whi[(size_t)m * HID * HID + (size_t)n * HID + k] =
            __float2half(tile[tx][ty + i]);
    }
}

// ---------------- projection: h = fp16(x @ Wp + bp) ----------------
__global__ void __launch_bounds__(256) proj_kernel(const float* __restrict__ x,
                                                   const float* __restrict__ Wp,
                                                   const float* __restrict__ bp) {
    __shared__ float xs[32][IN_DIM];
    __shared__ float ws[IN_DIM * HID];
    const int tid = threadIdx.x;
    for (int i = tid; i < IN_DIM * HID; i += 256) ws[i] = Wp[i];
    const int row0 = blockIdx.x * 32;
    for (int i = tid; i < 32 * IN_DIM; i += 256) {
        int r = i / IN_DIM, k = i % IN_DIM;
        xs[r][k] = (row0 + r < N_NODES) ? x[(row0 + r) * IN_DIM + k] : 0.f;
    }
    __syncthreads();
    float acc[32];
#pragma unroll
    for (int r = 0; r < 32; r++) acc[r] = 0.f;
    const int col = tid;
#pragma unroll
    for (int k = 0; k < IN_DIM; k++) {
        float w = ws[k * HID + col];
#pragma unroll
        for (int r = 0; r < 32; r++) acc[r] = fmaf(xs[r][k], w, acc[r]);
    }
    const float b = bp[col];
    for (int r = 0; r < 32; r++) {
        int rr = row0 + r;
        if (rr < N_NODES) g_h[rr * HID + col] = __float2half(acc[r] + b);
    }
}

// ---------------- CSR build ----------------
__global__ void count_kernel(const int* __restrict__ dst) {
    int e = blockIdx.x * blockDim.x + threadIdx.x;
    if (e < N_EDGES) atomicAdd(&g_deg[dst[e]], 1);
}
__global__ void __launch_bounds__(1024) scan_kernel() {
    const int CH = (N_NODES + 1023) / 1024;
    const int tid = threadIdx.x;
    const int base = tid * CH;
    int s = 0;
    for (int i = 0; i < CH; i++) {
        int idx = base + i;
        if (idx < N_NODES) s += g_deg[idx];
    }
    __shared__ int bs[1024];
    bs[tid] = s;
    __syncthreads();
    for (int off = 1; off < 1024; off <<= 1) {
        int v = (tid >= off) ? bs[tid - off] : 0;
        __syncthreads();
        bs[tid] += v;
        __syncthreads();
    }
    int running = bs[tid] - s;
    for (int i = 0; i < CH; i++) {
        int idx = base + i;
        if (idx < N_NODES) {
            g_off[idx] = running;
            running += g_deg[idx];
            g_fill[idx] = 0;
        }
    }
    if (tid == 1023) g_off[N_NODES] = bs[1023];
}
__global__ void fill_kernel(const int* __restrict__ src, const int* __restrict__ dst) {
    int e = blockIdx.x * blockDim.x + threadIdx.x;
    if (e >= N_EDGES) return;
    int d = dst[e];
    int pos = g_off[d] + atomicAdd(&g_fill[d], 1);
    g_csr[pos] = src[e];
}

// ------- gather: zp[n] = fp16((1+eps)*f(in[n]) + sum f(in[j])); zero stats/deg -------
template <bool BN>
__global__ void __launch_bounds__(256) gather_kernel(const float* __restrict__ eps, int l,
                                                     const float* __restrict__ gammas,
                                                     const float* __restrict__ betas) {
    const int tid = threadIdx.x;
    if (blockIdx.x == 0) {
        g_colsum2[l & 1][tid] = 0.f;
        g_colsq2[l & 1][tid] = 0.f;
    }
    if (!BN) {  // layer 0: reset degree counters for the next graph replay
        int zi = blockIdx.x * 256 + tid;
        if (blockIdx.x < (N_NODES + 255) / 256 && zi < N_NODES) g_deg[zi] = 0;
    }
    const int node = blockIdx.x * 4 + (tid >> 6);
    const int lane = tid & 63;
    if (node >= N_NODES) return;
    const float s = 1.f + eps[l];
    const int lo = g_off[node];
    const int hi = g_off[node + 1];
    const uint2* in2 = reinterpret_cast<const uint2*>(BN ? g_z : g_h);
    float4 sc, sh;
    if (BN) {
        const int pp = (l - 1) & 1;
        const float inv = 1.f / (float)N_NODES;
        float scv[4], shv[4];
#pragma unroll
        for (int j = 0; j < 4; j++) {
            int c = lane * 4 + j;
            float mu = g_colsum2[pp][c] * inv;
            float var = g_colsq2[pp][c] * inv - mu * mu;
            float rs = rsqrtf(var + BN_EPS);
            scv[j] = gammas[(l - 1) * HID + c] * rs;
            shv[j] = betas[(l - 1) * HID + c] - mu * scv[j];
        }
        sc = make_float4(scv[0], scv[1], scv[2], scv[3]);
        sh = make_float4(shv[0], shv[1], shv[2], shv[3]);
    }
    auto f = [&](float4 v) {
        if (BN) {
            v.x = fmaxf(fmaf(v.x, sc.x, sh.x), 0.f);
            v.y = fmaxf(fmaf(v.y, sc.y, sh.y), 0.f);
            v.z = fmaxf(fmaf(v.z, sc.z, sh.z), 0.f);
            v.w = fmaxf(fmaf(v.w, sc.w, sh.w), 0.f);
        }
        return v;
    };
    float4 a = f(unpack_h4(in2[node * 64 + lane]));
    a.x *= s; a.y *= s; a.z *= s; a.w *= s;
    for (int i = lo; i < hi; i++) {
        int sr = g_csr[i];
        float4 v = f(unpack_h4(in2[sr * 64 + lane]));
        a.x += v.x; a.y += v.y; a.z += v.z; a.w += v.w;
    }
    uint2 p;
    p.x = pack_h2(a.x, a.y);
    p.y = pack_h2(a.z, a.w);
    reinterpret_cast<uint2*>(g_zp)[node * 64 + lane] = p;
}

// ---------------- pooling with fused final BN+relu (stats parity 0) ----------------
__global__ void pool_kernel(const int* __restrict__ batch,
                            const float* __restrict__ gammas,
                            const float* __restrict__ betas) {
    const int g = blockIdx.x;
    const int col = threadIdx.x;
    __shared__ int s_lo, s_hi;
    if (col < 2) {
        int target = g + col;
        int lo = 0, hi = N_NODES;
        while (lo < hi) {
            int mid = (lo + hi) >> 1;
            if (batch[mid] < target) lo = mid + 1; else hi = mid;
        }
        if (col == 0) s_lo = lo; else s_hi = lo;
    }
    __syncthreads();
    const int lo = s_lo, hi = s_hi;
    const float inv = 1.f / (float)N_NODES;
    const float mu = g_colsum2[0][col] * inv;
    const float var = g_colsq2[0][col] * inv - mu * mu;
    const float rs = rsqrtf(var + BN_EPS);
    const float sc = gammas[(LAYERS - 1) * HID + col] * rs;
    const float sh = betas[(LAYERS - 1) * HID + col] - mu * sc;
    float s = 0.f;
    for (int r = lo; r < hi; r++)
        s += fmaxf(fmaf(__half2float(g_z[r * HID + col]), sc, sh), 0.f);
    g_pool[g * HID + col] = s / fmaxf((float)(hi - lo), 1.f);
}

// ---------------- readout SGEMM (fp32 SIMT, small M) ----------------
template <bool RELU>
__global__ void __launch_bounds__(256) sgemm_kernel(const float* __restrict__ A,
                                                    const float* __restrict__ B,
                                                    const float* __restrict__ bias,
                                                    float* __restrict__ C,
                                                    int M, int N, int K) {
    __shared__ float As[8][128];
    __shared__ float Bs[8][128];
    const int tid = threadIdx.x;
    const int row0 = blockIdx.x * 128;
    const int col0 = blockIdx.y * 128;
    const int tr = (tid >> 4) << 3;
    const int tc = (tid & 15) << 3;
    const int arow = tid >> 1;
    const int ak4 = (tid & 1) * 4;
    const int brow = tid >> 5;
    const int bcol = (tid & 31) * 4;
    float acc[8][8];
#pragma unroll
    for (int i = 0; i < 8; i++)
#pragma unroll
        for (int j = 0; j < 8; j++) acc[i][j] = 0.f;
    const int gar = row0 + arow;
    const bool arow_ok = (gar < M);
    for (int k0 = 0; k0 < K; k0 += 8) {
        float4 av = make_float4(0.f, 0.f, 0.f, 0.f);
        if (arow_ok)
            av = *reinterpret_cast<const float4*>(A + (size_t)gar * K + k0 + ak4);
        As[ak4 + 0][arow] = av.x;
        As[ak4 + 1][arow] = av.y;
        As[ak4 + 2][arow] = av.z;
        As[ak4 + 3][arow] = av.w;
        float4 bv = *reinterpret_cast<const float4*>(B + (size_t)(k0 + brow) * N + col0 + bcol);
        *reinterpret_cast<float4*>(&Bs[brow][bcol]) = bv;
        __syncthreads();
#pragma unroll
        for (int k = 0; k < 8; k++) {
            float ra[8], rb[8];
#pragma unroll
            for (int i = 0; i < 8; i++) ra[i] = As[k][tr + i];
#pragma unroll
            for (int j = 0; j < 8; j++) rb[j] = Bs[k][tc + j];
#pragma unroll
            for (int i = 0; i < 8; i++)
#pragma unroll
                for (int j = 0; j < 8; j++) acc[i][j] = fmaf(ra[i], rb[j], acc[i][j]);
        }
        __syncthreads();
    }
#pragma unroll
    for (int i = 0; i < 8; i++) {
        int r = row0 + tr + i;
        if (r >= M) break;
#pragma unroll
        for (int j = 0; j < 8; j += 4) {
            float4 v;
            v.x = acc[i][j + 0] + bias[col0 + tc + j + 0];
            v.y = acc[i][j + 1] + bias[col0 + tc + j + 1];
            v.z = acc[i][j + 2] + bias[col0 + tc + j + 2];
            v.w = acc[i][j + 3] + bias[col0 + tc + j + 3];
            if (RELU) {
                v.x = fmaxf(v.x, 0.f); v.y = fmaxf(v.y, 0.f);
                v.z = fmaxf(v.z, 0.f); v.w = fmaxf(v.w, 0.f);
            }
            *reinterpret_cast<float4*>(C + (size_t)r * N + col0 + tc + j) = v;
        }
    }
}

__global__ void readout2_kernel(const float* __restrict__ Wr2,
                                const float* __restrict__ br2,
                                float* __restrict__ out) {
    __shared__ float red[256];
    const int g = blockIdx.x;
    const int t = threadIdx.x;
    red[t] = g_r1[g * HID + t] * Wr2[t];
    __syncthreads();
    for (int s = 128; s > 0; s >>= 1) {
        if (t < s) red[t] += red[t + s];
        __syncthreads();
    }
    if (t == 0) out[g] = red[0] + br2[0];
}

// ---------------- host launcher ----------------
extern "C" void kernel_launch(void* const* d_in, const int* in_sizes, int n_in,
                              void* d_out, int out_size) {
    const float* x      = (const float*)d_in[0];
    const int*   ei     = (const int*)d_in[1];
    const int*   batch  = (const int*)d_in[2];
    const float* Wp     = (const float*)d_in[3];
    const float* bp     = (const float*)d_in[4];
    const float* eps    = (const float*)d_in[5];
    const float* W1s    = (const float*)d_in[6];
    const float* b1s    = (const float*)d_in[7];
    const float* W2s    = (const float*)d_in[8];
    const float* b2s    = (const float*)d_in[9];
    const float* gammas = (const float*)d_in[10];
    const float* betas  = (const float*)d_in[11];
    const float* Wr1    = (const float*)d_in[12];
    const float* br1    = (const float*)d_in[13];
    const float* Wr2    = (const float*)d_in[14];
    const float* br2    = (const float*)d_in[15];
    float* out = (float*)d_out;

    const int* src = ei;
    const int* dst = ei + N_EDGES;

    void *p_z, *p_zp, *p_tp, *p_pool, *p_r1, *p_whi, *p_cs, *p_cq;
    cudaGetSymbolAddress(&p_z, g_z);
    cudaGetSymbolAddress(&p_zp, g_zp);
    cudaGetSymbolAddress(&p_tp, g_tp);
    cudaGetSymbolAddress(&p_pool, g_pool);
    cudaGetSymbolAddress(&p_r1, g_r1);
    cudaGetSymbolAddress(&p_whi, g_whi);
    cudaGetSymbolAddress(&p_cs, g_colsum2);
    cudaGetSymbolAddress(&p_cq, g_colsq2);
    __half* dz = (__half*)p_z;
    __half* dzp = (__half*)p_zp;
    __half* dtp = (__half*)p_tp;
    float* dpool = (float*)p_pool;
    float* dr1 = (float*)p_r1;
    __half* dwhi = (__half*)p_whi;
    float* dcs = (float*)p_cs;
    float* dcq = (float*)p_cq;

    cudaFuncSetAttribute(gemm_mma_kernel<0>,
                         cudaFuncAttributeMaxDynamicSharedMemorySize, GEMM_SMEM);
    cudaFuncSetAttribute(gemm_mma_kernel<1>,
                         cudaFuncAttributeMaxDynamicSharedMemorySize, GEMM_SMEM);

    // CSR build + W convert + projection (g_deg re-zeroed by layer-0 gather)
    count_kernel<<<(N_EDGES + 255) / 256, 256>>>(dst);
    scan_kernel<<<1, 1024>>>();
    fill_kernel<<<(N_EDGES + 255) / 256, 256>>>(src, dst);
    wsplit_kernel<<<dim3(8, 8, 2 * LAYERS), dim3(32, 8)>>>(W1s, W2s);
    proj_kernel<<<(N_NODES + 31) / 32, 256>>>(x, Wp, bp);

    const dim3 ggrid((N_NODES + 127) / 128, 2);
    const size_t WSZ = (size_t)HID * HID;

    for (int l = 0; l < LAYERS; l++) {
        if (l == 0)
            gather_kernel<false><<<(N_NODES + 3) / 4, 256>>>(eps, l, gammas, betas);
        else
            gather_kernel<true><<<(N_NODES + 3) / 4, 256>>>(eps, l, gammas, betas);
        gemm_mma_kernel<1><<<ggrid, 256, GEMM_SMEM>>>(
            dzp, dwhi + (2 * l) * WSZ, b1s + l * HID, dtp, nullptr, nullptr, N_NODES);
        gemm_mma_kernel<0><<<ggrid, 256, GEMM_SMEM>>>(
            dtp, dwhi + (2 * l + 1) * WSZ, b2s + l * HID,
            dz, dcs + (l & 1) * HID, dcq + (l & 1) * HID, N_NODES);
    }

    pool_kernel<<<N_GRAPHS, 256>>>(batch, gammas, betas);

    const dim3 rgrid(N_GRAPHS / 128, HID / 128);
    sgemm_kernel<true><<<rgrid, 256>>>(dpool, Wr1, br1, dr1, N_GRAPHS, HID, HID);
    readout2_kernel<<<N_GRAPHS, 256>>>(Wr2, br2, out);
}

// round 13
// speedup vs baseline: 1.7419x; 1.0483x over previous
#include <cuda_runtime.h>
#include <cuda_fp16.h>
#include <cuda_bf16.h>
#include <cstdint>

#define N_NODES 100000
#define N_EDGES 300000
#define N_GRAPHS 2048
#define IN_DIM 38
#define HID 256
#define LAYERS 5
#define BN_EPS 1e-5f

// ---------------- device scratch ----------------
__device__ __half g_h[N_NODES * HID];         // fp16 features (proj out)
__device__ __half g_z[N_NODES * HID];         // fp16 GEMM2 output (pre-BN)
__device__ __half g_zp[N_NODES * HID];        // fp16 GEMM1 input
__device__ __half g_tp[N_NODES * HID];        // fp16 GEMM1 out / GEMM2 in
__device__ __half g_whi[2 * LAYERS * HID * HID];  // W^T fp16, [mat][n][k]
__device__ float g_colsum2[2][HID];
__device__ float g_colsq2[2][HID];
__device__ float g_pool[N_GRAPHS * HID];
__device__ float g_r1[N_GRAPHS * HID];
__device__ int g_deg[N_NODES];                // zero-init; re-zeroed by layer-0 gather
__device__ int g_fill[N_NODES];
__device__ int g_off[N_NODES + 1];
__device__ int g_csr[N_EDGES];

__device__ __forceinline__ uint32_t smem_u32(const void* p) {
    uint32_t a;
    asm("{ .reg .u64 t; cvta.to.shared.u64 t, %1; cvt.u32.u64 %0, t; }"
        : "=r"(a) : "l"(p));
    return a;
}

__device__ __forceinline__ uint32_t pack_h2(float x, float y) {
    __half2 h = __floats2half2_rn(x, y);
    return *reinterpret_cast<uint32_t*>(&h);
}

__device__ __forceinline__ float4 unpack_h4(uint2 u) {
    __half2 h0 = *reinterpret_cast<__half2*>(&u.x);
    __half2 h1 = *reinterpret_cast<__half2*>(&u.y);
    float2 f0 = __half22float2(h0);
    float2 f1 = __half22float2(h1);
    return make_float4(f0.x, f0.y, f1.x, f1.y);
}

#define MMA_F16(c, a0, a1, a2, a3, b0, b1)                                     \
    asm volatile(                                                              \
        "mma.sync.aligned.m16n8k16.row.col.f32.f16.f16.f32 "                   \
        "{%0,%1,%2,%3}, {%4,%5,%6,%7}, {%8,%9}, {%0,%1,%2,%3};"                \
        : "+f"((c)[0]), "+f"((c)[1]), "+f"((c)[2]), "+f"((c)[3])               \
        : "r"(a0), "r"(a1), "r"(a2), "r"(a3), "r"(b0), "r"(b1))

#define LDMX4(r, addr)                                                         \
    asm volatile("ldmatrix.sync.aligned.m8n8.x4.shared.b16 {%0,%1,%2,%3}, [%4];" \
        : "=r"((r)[0]), "=r"((r)[1]), "=r"((r)[2]), "=r"((r)[3]) : "r"(addr))

#define CP_ASYNC16(dst, src) \
    asm volatile("cp.async.ca.shared.global [%0], [%1], 16;" \
                 :: "r"(dst), "l"(src) : "memory")
#define CP_ASYNC16_Z(dst, src, n) \
    asm volatile("cp.async.ca.shared.global [%0], [%1], 16, %2;" \
                 :: "r"(dst), "l"(src), "r"(n) : "memory")
#define CP_COMMIT() asm volatile("cp.async.commit_group;" ::: "memory")

// BK=64: stage = A 128 rows x 144B (128B data + 16B pad) + B 128 x 144B
#define ROWB 144
#define STG 36864
#define A_ST(s)  ((s) * STG)
#define BH_ST(s) ((s) * STG + 18432)
#define GEMM_SMEM (2 * STG)

// ====== GEMM: C[M,256] = A_f16 @ W_f16[n][k]^T + bias ======
// OUTMODE 0: fp16 out (no relu) + fused fp32 stats; OUTMODE 1: relu + fp16 out.
template <int OUTMODE>
__global__ void __launch_bounds__(256, 2)
gemm_mma_kernel(const __half* __restrict__ Ap,
                const __half* __restrict__ Whi,
                const float* __restrict__ bias,
                void* __restrict__ Cout,
                float* __restrict__ colsum, float* __restrict__ colsq, int M) {
    extern __shared__ char sm[];
    const uint32_t smb = smem_u32(sm);
    const int tid = threadIdx.x;
    const int lane = tid & 31;
    const int wid = tid >> 5;
    const int wm = wid & 3;
    const int wn = wid >> 2;
    const int gq = lane >> 2;
    const int tq = lane & 3;
    const int row0 = blockIdx.x * 128;
    const int col0 = blockIdx.y * 128;

    float acc[2][8][4];
#pragma unroll
    for (int i = 0; i < 2; i++)
#pragma unroll
        for (int n = 0; n < 8; n++)
#pragma unroll
            for (int q = 0; q < 4; q++) acc[i][n][q] = 0.f;

    auto load_chunk = [&](int c, int s) {
        const int k0 = c * 64;
        // A: 128 rows x 128B fp16
#pragma unroll
        for (int i = 0; i < 4; i++) {
            int idx = tid + 256 * i;
            int r = idx >> 3, q = idx & 7;
            int gr = row0 + r;
            int nb = (gr < M) ? 16 : 0;
            int grc = (gr < M) ? gr : (M - 1);
            const char* src = (const char*)(Ap + (size_t)grc * HID + k0 + q * 8);
            CP_ASYNC16_Z(smb + A_ST(s) + r * ROWB + q * 16, src, nb);
        }
        // B: 128 n-rows x 128B
#pragma unroll
        for (int i = 0; i < 4; i++) {
            int idx = tid + 256 * i;
            int r = idx >> 3, q = idx & 7;
            const char* src = (const char*)(Whi + (size_t)(col0 + r) * HID + k0 + q * 8);
            CP_ASYNC16(smb + BH_ST(s) + r * ROWB + q * 16, src);
        }
        CP_COMMIT();
    };

    // ldmatrix lane mappings
    const int a_lrow = lane & 15;
    const int a_koff = (lane >> 4) * 16;
    const int b_lrow = ((lane & 16) >> 1) + (lane & 7);
    const int b_koff = ((lane >> 3) & 1) * 16;

    auto compute = [&](int s) {
#pragma unroll
        for (int j = 0; j < 4; j++) {    // 4 k16 steps per BK=64 chunk
            uint32_t a[2][4];
#pragma unroll
            for (int i = 0; i < 2; i++) {
                uint32_t ro = (uint32_t)(wm * 32 + i * 16 + a_lrow) * ROWB + j * 32 + a_koff;
                LDMX4(a[i], smb + A_ST(s) + ro);
            }
#pragma unroll
            for (int np = 0; np < 4; np++) {
                uint32_t bh[4];
                uint32_t bo = (uint32_t)(wn * 64 + np * 16 + b_lrow) * ROWB + j * 32 + b_koff;
                LDMX4(bh, smb + BH_ST(s) + bo);
#pragma unroll
                for (int i = 0; i < 2; i++) {
                    MMA_F16(acc[i][np * 2],     a[i][0], a[i][1], a[i][2], a[i][3], bh[0], bh[1]);
                    MMA_F16(acc[i][np * 2 + 1], a[i][0], a[i][1], a[i][2], a[i][3], bh[2], bh[3]);
                }
            }
        }
    };

    // 2-stage pipeline over 4 chunks, one sync per chunk.
    load_chunk(0, 0);
    load_chunk(1, 1);

#pragma unroll 1
    for (int c = 0; c < 4; c++) {
        if (c < 3) asm volatile("cp.async.wait_group 1;" ::: "memory");
        else       asm volatile("cp.async.wait_group 0;" ::: "memory");
        __syncthreads();
        compute(c & 1);
        if (c + 2 < 4) {
            __syncthreads();            // stage (c&1) fully consumed before refill
            load_chunk(c + 2, c & 1);
        }
    }

    // ---------------- epilogue ----------------
    uint32_t* C = (uint32_t*)Cout;   // fp16 pairs
    if (OUTMODE == 1) {
#pragma unroll
        for (int i = 0; i < 2; i++) {
            int r0 = row0 + wm * 32 + i * 16 + gq;
#pragma unroll
            for (int n = 0; n < 8; n++) {
                int col = col0 + wn * 64 + n * 8 + tq * 2;
                float b0 = bias[col], b1 = bias[col + 1];
                float v0 = fmaxf(acc[i][n][0] + b0, 0.f);
                float v1 = fmaxf(acc[i][n][1] + b1, 0.f);
                float v2 = fmaxf(acc[i][n][2] + b0, 0.f);
                float v3 = fmaxf(acc[i][n][3] + b1, 0.f);
                if (r0 < M)
                    C[(size_t)r0 * (HID / 2) + (col >> 1)] = pack_h2(v0, v1);
                if (r0 + 8 < M)
                    C[(size_t)(r0 + 8) * (HID / 2) + (col >> 1)] = pack_h2(v2, v3);
            }
        }
    } else {
        float s[16], q[16];
#pragma unroll
        for (int k = 0; k < 16; k++) { s[k] = 0.f; q[k] = 0.f; }
#pragma unroll
        for (int i = 0; i < 2; i++) {
            int r0 = row0 + wm * 32 + i * 16 + gq;
            bool ok0 = (r0 < M), ok1 = (r0 + 8 < M);
#pragma unroll
            for (int n = 0; n < 8; n++) {
                int col = col0 + wn * 64 + n * 8 + tq * 2;
                float b0 = bias[col], b1 = bias[col + 1];
                float v0 = acc[i][n][0] + b0, v1 = acc[i][n][1] + b1;
                float v2 = acc[i][n][2] + b0, v3 = acc[i][n][3] + b1;
                if (ok0)
                    C[(size_t)r0 * (HID / 2) + (col >> 1)] = pack_h2(v0, v1);
                if (ok1)
                    C[(size_t)(r0 + 8) * (HID / 2) + (col >> 1)] = pack_h2(v2, v3);
                float a0 = ok0 ? v0 : 0.f, a1 = ok0 ? v1 : 0.f;
                float a2 = ok1 ? v2 : 0.f, a3 = ok1 ? v3 : 0.f;
                s[n * 2 + 0] += a0 + a2;
                s[n * 2 + 1] += a1 + a3;
                q[n * 2 + 0] += a0 * a0 + a2 * a2;
                q[n * 2 + 1] += a1 * a1 + a3 * a3;
            }
        }
#pragma unroll
        for (int k = 0; k < 16; k++) {
#pragma unroll
            for (int off = 4; off < 32; off <<= 1) {
                s[k] += __shfl_xor_sync(0xffffffffu, s[k], off);
                q[k] += __shfl_xor_sync(0xffffffffu, q[k], off);
            }
        }
        if (lane < 4) {
#pragma unroll
            for (int k = 0; k < 16; k++) {
                int col = col0 + wn * 64 + (k >> 1) * 8 + lane * 2 + (k & 1);
                atomicAdd(&colsum[col], s[k]);
                atomicAdd(&colsq[col], q[k]);
            }
        }
    }
}

// ---------------- W transpose to fp16 (once per launch) ----------------
__global__ void wsplit_kernel(const float* __restrict__ W1s,
                              const float* __restrict__ W2s) {
    __shared__ float tile[32][33];
    const int m = blockIdx.z;
    const float* W = (m & 1) ? (W2s + (size_t)(m >> 1) * HID * HID)
                             : (W1s + (size_t)(m >> 1) * HID * HID);
    const int kb = blockIdx.y * 32, nb = blockIdx.x * 32;
    const int tx = threadIdx.x, ty = threadIdx.y;
#pragma unroll
    for (int i = 0; i < 32; i += 8)
        tile[ty + i][tx] = W[(size_t)(kb + ty + i) * HID + nb + tx];
    __syncthreads();
#pragma unroll
    for (int i = 0; i < 32; i += 8) {
        int n = nb + ty + i, k = kb + tx;
        g_whi[(size_t)m * HID * HID + (size_t)n * HID + k] =
            __float2half(tile[tx][ty + i]);
    }
}

// ---------------- projection: h = fp16(x @ Wp + bp) ----------------
__global__ void __launch_bounds__(256) proj_kernel(const float* __restrict__ x,
                                                   const float* __restrict__ Wp,
                                                   const float* __restrict__ bp) {
    __shared__ float xs[32][IN_DIM];
    __shared__ float ws[IN_DIM * HID];
    const int tid = threadIdx.x;
    for (int i = tid; i < IN_DIM * HID; i += 256) ws[i] = Wp[i];
    const int row0 = blockIdx.x * 32;
    for (int i = tid; i < 32 * IN_DIM; i += 256) {
        int r = i / IN_DIM, k = i % IN_DIM;
        xs[r][k] = (row0 + r < N_NODES) ? x[(row0 + r) * IN_DIM + k] : 0.f;
    }
    __syncthreads();
    float acc[32];
#pragma unroll
    for (int r = 0; r < 32; r++) acc[r] = 0.f;
    const int col = tid;
#pragma unroll
    for (int k = 0; k < IN_DIM; k++) {
        float w = ws[k * HID + col];
#pragma unroll
        for (int r = 0; r < 32; r++) acc[r] = fmaf(xs[r][k], w, acc[r]);
    }
    const float b = bp[col];
    for (int r = 0; r < 32; r++) {
        int rr = row0 + r;
        if (rr < N_NODES) g_h[rr * HID + col] = __float2half(acc[r] + b);
    }
}

// ---------------- CSR build ----------------
__global__ void count_kernel(const int* __restrict__ dst) {
    int e = blockIdx.x * blockDim.x + threadIdx.x;
    if (e < N_EDGES) atomicAdd(&g_deg[dst[e]], 1);
}
__global__ void __launch_bounds__(1024) scan_kernel() {
    const int CH = (N_NODES + 1023) / 1024;
    const int tid = threadIdx.x;
    const int base = tid * CH;
    int s = 0;
    for (int i = 0; i < CH; i++) {
        int idx = base + i;
        if (idx < N_NODES) s += g_deg[idx];
    }
    __shared__ int bs[1024];
    bs[tid] = s;
    __syncthreads();
    for (int off = 1; off < 1024; off <<= 1) {
        int v = (tid >= off) ? bs[tid - off] : 0;
        __syncthreads();
        bs[tid] += v;
        __syncthreads();
    }
    int running = bs[tid] - s;
    for (int i = 0; i < CH; i++) {
        int idx = base + i;
        if (idx < N_NODES) {
            g_off[idx] = running;
            running += g_deg[idx];
            g_fill[idx] = 0;
        }
    }
    if (tid == 1023) g_off[N_NODES] = bs[1023];
}
__global__ void fill_kernel(const int* __restrict__ src, const int* __restrict__ dst) {
    int e = blockIdx.x * blockDim.x + threadIdx.x;
    if (e >= N_EDGES) return;
    int d = dst[e];
    int pos = g_off[d] + atomicAdd(&g_fill[d], 1);
    g_csr[pos] = src[e];
}

// ------- gather: zp[n] = fp16((1+eps)*f(in[n]) + sum f(in[j])); zero stats/deg -------
template <bool BN>
__global__ void __launch_bounds__(256) gather_kernel(const float* __restrict__ eps, int l,
                                                     const float* __restrict__ gammas,
                                                     const float* __restrict__ betas) {
    const int tid = threadIdx.x;
    if (blockIdx.x == 0) {
        g_colsum2[l & 1][tid] = 0.f;
        g_colsq2[l & 1][tid] = 0.f;
    }
    if (!BN) {  // layer 0: reset degree counters for the next graph replay
        int zi = blockIdx.x * 256 + tid;
        if (blockIdx.x < (N_NODES + 255) / 256 && zi < N_NODES) g_deg[zi] = 0;
    }
    const int node = blockIdx.x * 4 + (tid >> 6);
    const int lane = tid & 63;
    if (node >= N_NODES) return;
    const float s = 1.f + eps[l];
    const int lo = g_off[node];
    const int hi = g_off[node + 1];
    const uint2* in2 = reinterpret_cast<const uint2*>(BN ? g_z : g_h);
    float4 sc, sh;
    if (BN) {
        const int pp = (l - 1) & 1;
        const float inv = 1.f / (float)N_NODES;
        float scv[4], shv[4];
#pragma unroll
        for (int j = 0; j < 4; j++) {
            int c = lane * 4 + j;
            float mu = g_colsum2[pp][c] * inv;
            float var = g_colsq2[pp][c] * inv - mu * mu;
            float rs = rsqrtf(var + BN_EPS);
            scv[j] = gammas[(l - 1) * HID + c] * rs;
            shv[j] = betas[(l - 1) * HID + c] - mu * scv[j];
        }
        sc = make_float4(scv[0], scv[1], scv[2], scv[3]);
        sh = make_float4(shv[0], shv[1], shv[2], shv[3]);
    }
    auto f = [&](float4 v) {
        if (BN) {
            v.x = fmaxf(fmaf(v.x, sc.x, sh.x), 0.f);
            v.y = fmaxf(fmaf(v.y, sc.y, sh.y), 0.f);
            v.z = fmaxf(fmaf(v.z, sc.z, sh.z), 0.f);
            v.w = fmaxf(fmaf(v.w, sc.w, sh.w), 0.f);
        }
        return v;
    };
    float4 a = f(unpack_h4(in2[node * 64 + lane]));
    a.x *= s; a.y *= s; a.z *= s; a.w *= s;
    for (int i = lo; i < hi; i++) {
        int sr = g_csr[i];
        float4 v = f(unpack_h4(in2[sr * 64 + lane]));
        a.x += v.x; a.y += v.y; a.z += v.z; a.w += v.w;
    }
    uint2 p;
    p.x = pack_h2(a.x, a.y);
    p.y = pack_h2(a.z, a.w);
    reinterpret_cast<uint2*>(g_zp)[node * 64 + lane] = p;
}

// ---------------- pooling with fused final BN+relu (stats parity 0) ----------------
__global__ void pool_kernel(const int* __restrict__ batch,
                            const float* __restrict__ gammas,
                            const float* __restrict__ betas) {
    const int g = blockIdx.x;
    const int col = threadIdx.x;
    __shared__ int s_lo, s_hi;
    if (col < 2) {
        int target = g + col;
        int lo = 0, hi = N_NODES;
        while (lo < hi) {
            int mid = (lo + hi) >> 1;
            if (batch[mid] < target) lo = mid + 1; else hi = mid;
        }
        if (col == 0) s_lo = lo; else s_hi = lo;
    }
    __syncthreads();
    const int lo = s_lo, hi = s_hi;
    const float inv = 1.f / (float)N_NODES;
    const float mu = g_colsum2[0][col] * inv;
    const float var = g_colsq2[0][col] * inv - mu * mu;
    const float rs = rsqrtf(var + BN_EPS);
    const float sc = gammas[(LAYERS - 1) * HID + col] * rs;
    const float sh = betas[(LAYERS - 1) * HID + col] - mu * sc;
    float s = 0.f;
    for (int r = lo; r < hi; r++)
        s += fmaxf(fmaf(__half2float(g_z[r * HID + col]), sc, sh), 0.f);
    g_pool[g * HID + col] = s / fmaxf((float)(hi - lo), 1.f);
}

// ---------------- readout SGEMM (fp32 SIMT, small M) ----------------
template <bool RELU>
__global__ void __launch_bounds__(256) sgemm_kernel(const float* __restrict__ A,
                                                    const float* __restrict__ B,
                                                    const float* __restrict__ bias,
                                                    float* __restrict__ C,
                                                    int M, int N, int K) {
    __shared__ float As[8][128];
    __shared__ float Bs[8][128];
    const int tid = threadIdx.x;
    const int row0 = blockIdx.x * 128;
    const int col0 = blockIdx.y * 128;
    const int tr = (tid >> 4) << 3;
    const int tc = (tid & 15) << 3;
    const int arow = tid >> 1;
    const int ak4 = (tid & 1) * 4;
    const int brow = tid >> 5;
    const int bcol = (tid & 31) * 4;
    float acc[8][8];
#pragma unroll
    for (int i = 0; i < 8; i++)
#pragma unroll
        for (int j = 0; j < 8; j++) acc[i][j] = 0.f;
    const int gar = row0 + arow;
    const bool arow_ok = (gar < M);
    for (int k0 = 0; k0 < K; k0 += 8) {
        float4 av = make_float4(0.f, 0.f, 0.f, 0.f);
        if (arow_ok)
            av = *reinterpret_cast<const float4*>(A + (size_t)gar * K + k0 + ak4);
        As[ak4 + 0][arow] = av.x;
        As[ak4 + 1][arow] = av.y;
        As[ak4 + 2][arow] = av.z;
        As[ak4 + 3][arow] = av.w;
        float4 bv = *reinterpret_cast<const float4*>(B + (size_t)(k0 + brow) * N + col0 + bcol);
        *reinterpret_cast<float4*>(&Bs[brow][bcol]) = bv;
        __syncthreads();
#pragma unroll
        for (int k = 0; k < 8; k++) {
            float ra[8], rb[8];
#pragma unroll
            for (int i = 0; i < 8; i++) ra[i] = As[k][tr + i];
#pragma unroll
            for (int j = 0; j < 8; j++) rb[j] = Bs[k][tc + j];
#pragma unroll
            for (int i = 0; i < 8; i++)
#pragma unroll
                for (int j = 0; j < 8; j++) acc[i][j] = fmaf(ra[i], rb[j], acc[i][j]);
        }
        __syncthreads();
    }
#pragma unroll
    for (int i = 0; i < 8; i++) {
        int r = row0 + tr + i;
        if (r >= M) break;
#pragma unroll
        for (int j = 0; j < 8; j += 4) {
            float4 v;
            v.x = acc[i][j + 0] + bias[col0 + tc + j + 0];
            v.y = acc[i][j + 1] + bias[col0 + tc + j + 1];
            v.z = acc[i][j + 2] + bias[col0 + tc + j + 2];
            v.w = acc[i][j + 3] + bias[col0 + tc + j + 3];
            if (RELU) {
                v.x = fmaxf(v.x, 0.f); v.y = fmaxf(v.y, 0.f);
                v.z = fmaxf(v.z, 0.f); v.w = fmaxf(v.w, 0.f);
            }
            *reinterpret_cast<float4*>(C + (size_t)r * N + col0 + tc + j) = v;
        }
    }
}

__global__ void readout2_kernel(const float* __restrict__ Wr2,
                                const float* __restrict__ br2,
                                float* __restrict__ out) {
    __shared__ float red[256];
    const int g = blockIdx.x;
    const int t = threadIdx.x;
    red[t] = g_r1[g * HID + t] * Wr2[t];
    __syncthreads();
    for (int s = 128; s > 0; s >>= 1) {
        if (t < s) red[t] += red[t + s];
        __syncthreads();
    }
    if (t == 0) out[g] = red[0] + br2[0];
}

// ---------------- host launcher ----------------
extern "C" void kernel_launch(void* const* d_in, const int* in_sizes, int n_in,
                              void* d_out, int out_size) {
    const float* x      = (const float*)d_in[0];
    const int*   ei     = (const int*)d_in[1];
    const int*   batch  = (const int*)d_in[2];
    const float* Wp     = (const float*)d_in[3];
    const float* bp     = (const float*)d_in[4];
    const float* eps    = (const float*)d_in[5];
    const float* W1s    = (const float*)d_in[6];
    const float* b1s    = (const float*)d_in[7];
    const float* W2s    = (const float*)d_in[8];
    const float* b2s    = (const float*)d_in[9];
    const float* gammas = (const float*)d_in[10];
    const float* betas  = (const float*)d_in[11];
    const float* Wr1    = (const float*)d_in[12];
    const float* br1    = (const float*)d_in[13];
    const float* Wr2    = (const float*)d_in[14];
    const float* br2    = (const float*)d_in[15];
    float* out = (float*)d_out;

    const int* src = ei;
    const int* dst = ei + N_EDGES;

    void *p_z, *p_zp, *p_tp, *p_pool, *p_r1, *p_whi, *p_cs, *p_cq;
    cudaGetSymbolAddress(&p_z, g_z);
    cudaGetSymbolAddress(&p_zp, g_zp);
    cudaGetSymbolAddress(&p_tp, g_tp);
    cudaGetSymbolAddress(&p_pool, g_pool);
    cudaGetSymbolAddress(&p_r1, g_r1);
    cudaGetSymbolAddress(&p_whi, g_whi);
    cudaGetSymbolAddress(&p_cs, g_colsum2);
    cudaGetSymbolAddress(&p_cq, g_colsq2);
    __half* dz = (__half*)p_z;
    __half* dzp = (__half*)p_zp;
    __half* dtp = (__half*)p_tp;
    float* dpool = (float*)p_pool;
    float* dr1 = (float*)p_r1;
    __half* dwhi = (__half*)p_whi;
    float* dcs = (float*)p_cs;
    float* dcq = (float*)p_cq;

    cudaFuncSetAttribute(gemm_mma_kernel<0>,
                         cudaFuncAttributeMaxDynamicSharedMemorySize, GEMM_SMEM);
    cudaFuncSetAttribute(gemm_mma_kernel<1>,
                         cudaFuncAttributeMaxDynamicSharedMemorySize, GEMM_SMEM);

    // CSR build + W convert + projection (g_deg re-zeroed by layer-0 gather)
    count_kernel<<<(N_EDGES + 255) / 256, 256>>>(dst);
    scan_kernel<<<1, 1024>>>();
    fill_kernel<<<(N_EDGES + 255) / 256, 256>>>(src, dst);
    wsplit_kernel<<<dim3(8, 8, 2 * LAYERS), dim3(32, 8)>>>(W1s, W2s);
    proj_kernel<<<(N_NODES + 31) / 32, 256>>>(x, Wp, bp);

    const dim3 ggrid((N_NODES + 127) / 128, 2);
    const size_t WSZ = (size_t)HID * HID;

    for (int l = 0; l < LAYERS; l++) {
        if (l == 0)
            gather_kernel<false><<<(N_NODES + 3) / 4, 256>>>(eps, l, gammas, betas);
        else
            gather_kernel<true><<<(N_NODES + 3) / 4, 256>>>(eps, l, gammas, betas);
        gemm_mma_kernel<1><<<ggrid, 256, GEMM_SMEM>>>(
            dzp, dwhi + (2 * l) * WSZ, b1s + l * HID, dtp, nullptr, nullptr, N_NODES);
        gemm_mma_kernel<0><<<ggrid, 256, GEMM_SMEM>>>(
            dtp, dwhi + (2 * l + 1) * WSZ, b2s + l * HID,
            dz, dcs + (l & 1) * HID, dcq + (l & 1) * HID, N_NODES);
    }

    pool_kernel<<<N_GRAPHS, 256>>>(batch, gammas, betas);

    const dim3 rgrid(N_GRAPHS / 128, HID / 128);
    sgemm_kernel<true><<<rgrid, 256>>>(dpool, Wr1, br1, dr1, N_GRAPHS, HID, HID);
    readout2_kernel<<<N_GRAPHS, 256>>>(Wr2, br2, out);
}